// round 7
// baseline (speedup 1.0000x reference)
#include <cuda_runtime.h>
#include <cstdint>
#include <cstddef>

#define N_USERC 100000
#define M_ITEMC 50000
#define N_NODEC 150000
#define DD      64
#define BSEED   2048
#define SNB     20
#define M1ROWS  (BSEED*SNB)          // 40960
#define MROWS   (BSEED*SNB + BSEED)  // 43008
#define NFEAT   30000
#define VOCABC  20000

// ---------------- device scratch ----------
__device__ float g_x[(size_t)N_NODEC * DD];
__device__ float g_h[(size_t)MROWS * DD];
__device__ float g_pfe_u[(size_t)NFEAT * 64];
__device__ float g_pfe_i[(size_t)NFEAT * 64];
__device__ float g_gs[(size_t)N_NODEC * 64];
__device__ float g_tm[(size_t)N_NODEC * 96];
__device__ float g_Bu[(size_t)480 * 64];
__device__ float g_Bi[(size_t)1248 * 64];

__device__ __forceinline__ uint32_t f2tf(float v) {
    uint32_t r; asm("cvt.rna.tf32.f32 %0, %1;" : "=r"(r) : "f"(v)); return r;
}
__device__ __forceinline__ void mma_tf32(float c[4],
    uint32_t a0, uint32_t a1, uint32_t a2, uint32_t a3, uint32_t b0, uint32_t b1)
{
    asm volatile(
        "mma.sync.aligned.m16n8k8.row.col.f32.tf32.tf32.f32 "
        "{%0,%1,%2,%3},{%4,%5,%6,%7},{%8,%9},{%0,%1,%2,%3};"
        : "+f"(c[0]), "+f"(c[1]), "+f"(c[2]), "+f"(c[3])
        : "r"(a0), "r"(a1), "r"(a2), "r"(a3), "r"(b0), "r"(b1));
}
__device__ __forceinline__ uint32_t smem_u32(const void* p) {
    return (uint32_t)__cvta_generic_to_shared(p);
}
__device__ __forceinline__ void cp16(uint32_t dst, const void* src, int bytes) {
    asm volatile("cp.async.ca.shared.global [%0], [%1], 16, %2;\n"
                 :: "r"(dst), "l"(src), "r"(bytes));
}
__device__ __forceinline__ void cp_commit() {
    asm volatile("cp.async.commit_group;\n");
}
template<int N> __device__ __forceinline__ void cp_wait() {
    asm volatile("cp.async.wait_group %0;\n" :: "n"(N));
}

// ========== 4-stage pipelined GEMM: out = scale*A@B (+gs) ===================
// A assembled from up to 4 row-major regions (gaps -> zero). B dense [K x 64].
struct PArgs {
    const float* Ar[4];
    int ab[4], ae[4], ars[4];
    const float* B;
    const float* gs;               // epilogue add [row*64+col] or null
    float* out;
    int M, K; float scale;
};

__device__ __forceinline__ void compute32(float c[2][4][4],
    const float* Ad, const float* Bd, int wm, int wn, int lane)
{
    const int r0 = lane >> 2, q = lane & 3;
#pragma unroll
    for (int ks = 0; ks < 4; ks++) {
        const int kb = ks * 8;
        uint32_t a[2][4], b[4][2];
#pragma unroll
        for (int mi = 0; mi < 2; mi++) {
            int mr = wm * 32 + mi * 16 + r0;
            a[mi][0] = f2tf(Ad[mr * 36 + kb + q]);
            a[mi][1] = f2tf(Ad[(mr + 8) * 36 + kb + q]);
            a[mi][2] = f2tf(Ad[mr * 36 + kb + q + 4]);
            a[mi][3] = f2tf(Ad[(mr + 8) * 36 + kb + q + 4]);
        }
#pragma unroll
        for (int ni = 0; ni < 4; ni++) {
            int nc = wn * 32 + ni * 8 + r0;
            b[ni][0] = f2tf(Bd[(kb + q) * 72 + nc]);
            b[ni][1] = f2tf(Bd[(kb + q + 4) * 72 + nc]);
        }
#pragma unroll
        for (int mi = 0; mi < 2; mi++)
#pragma unroll
            for (int ni = 0; ni < 4; ni++)
                mma_tf32(c[mi][ni], a[mi][0], a[mi][1], a[mi][2], a[mi][3],
                         b[ni][0], b[ni][1]);
    }
}

__global__ void __launch_bounds__(256) pgemm(PArgs p)
{
    extern __shared__ float smp[];
    float* Asm = smp;                      // [4][128*36]
    float* Bsm = smp + 4 * 128 * 36;       // [4][32*72]

    const int tid = threadIdx.x, lane = tid & 31, wid = tid >> 5;
    const int wm = wid >> 1, wn = wid & 1;
    const int m0 = blockIdx.x * 128;

    auto issue = [&](int tile, int slot) {
        const int k0 = tile * 32;
        float* Ad = Asm + slot * (128 * 36);
        float* Bd = Bsm + slot * (32 * 72);
        // A: 128 rows x 8 chunks of 4 floats = 1024 chunks
#pragma unroll
        for (int j = 0; j < 4; j++) {
            int ch = tid + j * 256;
            int r = ch >> 3, cq = ch & 7;
            int col = k0 + cq * 4;
            int row = m0 + r;
            const float* src = p.Ar[0]; int bytes = 0;
            if (row < p.M) {
#pragma unroll
                for (int g = 0; g < 4; g++) {
                    if (col >= p.ab[g] && col < p.ae[g]) {
                        src = p.Ar[g] + (size_t)row * p.ars[g] + (col - p.ab[g]);
                        bytes = 16;
                    }
                }
            }
            cp16(smem_u32(Ad + r * 36 + cq * 4), src, bytes);
        }
        // B: 32 rows x 16 chunks of 4 floats = 512 chunks
#pragma unroll
        for (int j = 0; j < 2; j++) {
            int cb = tid + j * 256;
            int kr = cb >> 4, cq = cb & 15;
            cp16(smem_u32(Bd + kr * 72 + cq * 4),
                 p.B + (size_t)(k0 + kr) * 64 + cq * 4, 16);
        }
    };

    float c[2][4][4];
#pragma unroll
    for (int a = 0; a < 2; a++)
#pragma unroll
        for (int b = 0; b < 4; b++)
#pragma unroll
            for (int d = 0; d < 4; d++) c[a][b][d] = 0.f;

    const int nt = p.K / 32;       // K multiple of 32
    issue(0, 0); cp_commit();
    if (nt > 1) issue(1, 1);
    cp_commit();
    if (nt > 2) issue(2, 2);
    cp_commit();

    for (int t = 0; t < nt; t++) {
        cp_wait<2>();              // group t complete (2 newest may pend)
        __syncthreads();
        if (t + 3 < nt) issue(t + 3, (t + 3) & 3);
        cp_commit();               // keep group accounting uniform
        compute32(c, Asm + (t & 3) * (128 * 36), Bsm + (t & 3) * (32 * 72),
                  wm, wn, lane);
    }

    const int r0 = lane >> 2, q = lane & 3;
#pragma unroll
    for (int mi = 0; mi < 2; mi++)
#pragma unroll
        for (int ni = 0; ni < 4; ni++) {
            int col = wn * 32 + ni * 8 + 2 * q;
            int row = m0 + wm * 32 + mi * 16 + r0;
#pragma unroll
            for (int h = 0; h < 2; h++) {
                int rr = row + h * 8;
                if (rr < p.M) {
                    float v0 = c[mi][ni][h * 2]     * p.scale;
                    float v1 = c[mi][ni][h * 2 + 1] * p.scale;
                    if (p.gs) {
                        float2 g = *reinterpret_cast<const float2*>(
                            p.gs + (size_t)rr * 64 + col);
                        v0 += g.x; v1 += g.y;
                    }
                    *reinterpret_cast<float2*>(p.out + (size_t)rr * 64 + col) =
                        make_float2(v0, v1);
                }
            }
        }
}

// =================== pack padded dense B matrices ===========================
// user cols: [0,64) id | [64,364) w300 | [368,464) text | pad 480
// item cols: [0,64) id | [64,364) w300 | [368,464) text | [464,1232) s768 | 1248
__global__ void pack_kernel(const float* __restrict__ Wpu,
                            const float* __restrict__ Wpi)
{
    int i = blockIdx.x * 256 + threadIdx.x;
    if (i < 480 * 64) {
        int r = i >> 6, n = i & 63; float v = 0.f;
        if (r < 64)                    v = Wpu[(size_t)r * 64 + n];
        else if (r < 364)              v = Wpu[(size_t)(r + 160) * 64 + n];
        else if (r >= 368 && r < 464)  v = Wpu[(size_t)(r - 240) * 64 + n];
        g_Bu[i] = v;
    }
    if (i < 1248 * 64) {
        int r = i >> 6, n = i & 63; float v = 0.f;
        if (r < 64)                    v = Wpi[(size_t)r * 64 + n];
        else if (r < 364)              v = Wpi[(size_t)(r + 160) * 64 + n];
        else if (r >= 368 && r < 464)  v = Wpi[(size_t)(r - 240) * 64 + n];
        else if (r >= 464 && r < 1232) v = Wpi[(size_t)(r + 60) * 64 + n];
        g_Bi[i] = v;
    }
}

// ========== merged gather: gs = bias + numeric@Wnum(smem) + feat sums =======
// also writes tm[node][96] = per-source mean of raw word embeddings
__global__ void __launch_bounds__(256) gather_all(
    const int* __restrict__ ufi, const int* __restrict__ ifi,
    const int* __restrict__ uti, const int* __restrict__ iti,
    const float* __restrict__ unum, const float* __restrict__ inum,
    const float* __restrict__ Wnu, const float* __restrict__ Wni,
    const float* __restrict__ bpu, const float* __restrict__ bnu,
    const float* __restrict__ bpi, const float* __restrict__ bni,
    const float* __restrict__ pfeu, const float* __restrict__ pfei,
    const float* __restrict__ wemb,
    float* __restrict__ gs, float* __restrict__ tm)
{
    __shared__ float sW[2][640];   // Wnum 10x64
    __shared__ float sB[2][64];    // bproj + bnum
    const int tid = threadIdx.x;
    for (int i = tid; i < 640; i += 256) {
        sW[0][i] = __ldg(Wnu + i);
        sW[1][i] = __ldg(Wni + i);
    }
    if (tid < 64) {
        sB[0][tid] = __ldg(bpu + tid) + __ldg(bnu + tid);
        sB[1][tid] = __ldg(bpi + tid) + __ldg(bni + tid);
    }
    __syncthreads();

    int w = (blockIdx.x * 256 + tid) >> 5;
    int lane = tid & 31;
    if (w >= N_NODEC) return;
    const int it = (w >= N_USERC) ? 1 : 0;
    const int n  = it ? (w - N_USERC) : w;
    const int*   ti   = it ? iti : uti;
    const int*   fi   = it ? ifi : ufi;
    const float* nump = it ? inum : unum;
    const float* Pfe  = it ? pfei : pfeu;
    int c2 = lane * 2;

    // ---- text: raw word-emb means (lane = column 0..31) ----
#pragma unroll
    for (int s = 0; s < 3; s++) {
        float acc = 0.f;
#pragma unroll
        for (int t = 0; t < 8; t++) {
            int ix = __ldg(ti + (size_t)n * 24 + s * 8 + t);
            acc += __ldg(wemb + (size_t)ix * 32 + lane);
        }
        tm[(size_t)w * 96 + s * 32 + lane] = acc * 0.125f;
    }

    // ---- gs: bias + numeric (smem W) + projected-feat sums ----
    float2 acc = make_float2(sB[it][c2], sB[it][c2 + 1]);
#pragma unroll
    for (int d = 0; d < 10; d++) {
        float nv = __ldg(nump + (size_t)n * 10 + d);
        acc.x += nv * sW[it][d * 64 + c2];
        acc.y += nv * sW[it][d * 64 + c2 + 1];
    }
#pragma unroll
    for (int j = 0; j < 10; j++) {
        int ix = __ldg(fi + (size_t)n * 10 + j);
        float2 v = *reinterpret_cast<const float2*>(Pfe + (size_t)ix * 64 + c2);
        acc.x += v.x; acc.y += v.y;
    }
    *reinterpret_cast<float2*>(gs + (size_t)w * 64 + c2) = acc;
}

// =================== fused SAGE layer ======================================
__device__ __forceinline__ void compute_tile68(float c[2][4][4],
    const uint32_t (*Asrc)[68], int kbase, const uint32_t (*Bs)[72],
    int wm, int wn, int lane)
{
    const int r0 = lane >> 2, q = lane & 3;
#pragma unroll
    for (int ks = 0; ks < 2; ks++) {
        const int kb = ks * 8;
        uint32_t a[2][4], b[4][2];
#pragma unroll
        for (int mi = 0; mi < 2; mi++) {
            int mr = wm * 32 + mi * 16 + r0;
            a[mi][0] = Asrc[mr][kbase + kb + q];
            a[mi][1] = Asrc[mr + 8][kbase + kb + q];
            a[mi][2] = Asrc[mr][kbase + kb + q + 4];
            a[mi][3] = Asrc[mr + 8][kbase + kb + q + 4];
        }
#pragma unroll
        for (int ni = 0; ni < 4; ni++) {
            int nc = wn * 32 + ni * 8 + r0;
            b[ni][0] = Bs[kb + q][nc];
            b[ni][1] = Bs[kb + q + 4][nc];
        }
#pragma unroll
        for (int mi = 0; mi < 2; mi++)
#pragma unroll
            for (int ni = 0; ni < 4; ni++)
                mma_tf32(c[mi][ni], a[mi][0], a[mi][1], a[mi][2], a[mi][3],
                         b[ni][0], b[ni][1]);
    }
}

template<int L0>
__global__ void __launch_bounds__(256) layer_kernel(
    const int* __restrict__ neigh2, const int* __restrict__ neigh1,
    const int* __restrict__ seeds,
    const float* __restrict__ Wv, const float* __restrict__ bv,
    const float* __restrict__ Ww, const float* __restrict__ bw,
    float* __restrict__ outp, int M, int relu)
{
    extern __shared__ uint32_t dsm[];
    uint32_t (*Ms)[68] = (uint32_t(*)[68])dsm;
    uint32_t (*Ss)[68] = (uint32_t(*)[68])(dsm + 128 * 68);
    uint32_t (*Bs)[72] = (uint32_t(*)[72])(dsm + 2 * 128 * 68);
    float* sbv = (float*)(dsm + 2 * 128 * 68 + 16 * 72);
    float* sbw = sbv + 64;

    const int tid = threadIdx.x, lane = tid & 31, wid = tid >> 5;
    const int wm = wid >> 1, wn = wid & 1;
    const int m0 = blockIdx.x * 128;

    if (tid < 64) { sbv[tid] = bv[tid]; sbw[tid] = bw[tid]; }

#pragma unroll 1
    for (int rr = 0; rr < 16; ++rr) {
        int ln = wid * 16 + rr;
        int r = m0 + ln;
        float ax = 0.f, ay = 0.f;
        float2 self = make_float2(0.f, 0.f);
        if (r < M) {
            if (L0) {
                const int* idx = (r < M1ROWS) ? (neigh2 + (size_t)r * SNB)
                                              : (neigh1 + (size_t)(r - M1ROWS) * SNB);
#pragma unroll
                for (int j = 0; j < SNB; j++) {
                    int n = __ldg(idx + j);
                    float2 v = *reinterpret_cast<const float2*>(g_x + (size_t)n * 64 + lane * 2);
                    ax += v.x; ay += v.y;
                }
                int sn = (r < M1ROWS) ? __ldg(neigh1 + r) : __ldg(seeds + r - M1ROWS);
                self = *reinterpret_cast<const float2*>(g_x + (size_t)sn * 64 + lane * 2);
            } else {
#pragma unroll
                for (int j = 0; j < SNB; j++) {
                    float2 v = *reinterpret_cast<const float2*>(
                        g_h + (size_t)(r * SNB + j) * 64 + lane * 2);
                    ax += v.x; ay += v.y;
                }
                self = *reinterpret_cast<const float2*>(
                    g_h + (size_t)(M1ROWS + r) * 64 + lane * 2);
            }
            ax *= 0.05f; ay *= 0.05f;
        }
        Ms[ln][lane * 2]     = f2tf(ax);
        Ms[ln][lane * 2 + 1] = f2tf(ay);
        Ss[ln][lane * 2]     = f2tf(self.x);
        Ss[ln][lane * 2 + 1] = f2tf(self.y);
    }

    float ca[2][4][4];
#pragma unroll
    for (int a = 0; a < 2; a++)
#pragma unroll
        for (int b = 0; b < 4; b++)
#pragma unroll
            for (int d = 0; d < 4; d++) ca[a][b][d] = 0.f;

    for (int k0 = 0; k0 < 64; k0 += 16) {
        __syncthreads();
        for (int i = tid; i < 16 * 64; i += 256) {
            int kk = i >> 6, n = i & 63;
            Bs[kk][n] = f2tf(Wv[(size_t)(k0 + kk) * 64 + n]);
        }
        __syncthreads();
        compute_tile68(ca, Ms, k0, Bs, wm, wn, lane);
    }
    __syncthreads();

    {
        const int r0 = lane >> 2, q = lane & 3;
#pragma unroll
        for (int mi = 0; mi < 2; mi++)
#pragma unroll
            for (int ni = 0; ni < 4; ni++) {
                int col = wn * 32 + ni * 8 + 2 * q;
                int lr = wm * 32 + mi * 16 + r0;
#pragma unroll
                for (int h = 0; h < 2; h++) {
                    int lrow = lr + h * 8;
                    Ms[lrow][col]     = f2tf(ca[mi][ni][h * 2]     + sbv[col]);
                    Ms[lrow][col + 1] = f2tf(ca[mi][ni][h * 2 + 1] + sbv[col + 1]);
                }
            }
    }
    __syncthreads();

    float ch[2][4][4];
#pragma unroll
    for (int a = 0; a < 2; a++)
#pragma unroll
        for (int b = 0; b < 4; b++)
#pragma unroll
            for (int d = 0; d < 4; d++) ch[a][b][d] = 0.f;

    for (int k0 = 0; k0 < 128; k0 += 16) {
        __syncthreads();
        for (int i = tid; i < 16 * 64; i += 256) {
            int kk = i >> 6, n = i & 63;
            Bs[kk][n] = f2tf(Ww[(size_t)(k0 + kk) * 64 + n]);
        }
        __syncthreads();
        if (k0 < 64) compute_tile68(ch, Ss, k0,      Bs, wm, wn, lane);
        else         compute_tile68(ch, Ms, k0 - 64, Bs, wm, wn, lane);
    }

    const int r0 = lane >> 2, q = lane & 3;
#pragma unroll
    for (int mi = 0; mi < 2; mi++)
#pragma unroll
        for (int ni = 0; ni < 4; ni++) {
            int col = wn * 32 + ni * 8 + 2 * q;
            int row = m0 + wm * 32 + mi * 16 + r0;
#pragma unroll
            for (int h = 0; h < 2; h++) {
                int rr = row + h * 8;
                if (rr < M) {
                    float v0 = ch[mi][ni][h * 2]     + sbw[col];
                    float v1 = ch[mi][ni][h * 2 + 1] + sbw[col + 1];
                    if (relu) { v0 = fmaxf(v0, 0.f); v1 = fmaxf(v1, 0.f); }
                    *reinterpret_cast<float2*>(outp + (size_t)rr * 64 + col) =
                        make_float2(v0, v1);
                }
            }
        }
}

// ============================ launch =========================================
extern "C" void kernel_launch(void* const* d_in, const int* in_sizes, int n_in,
                              void* d_out, int out_size)
{
    const int*   seeds  = (const int*)d_in[0];
    const int*   neigh1 = (const int*)d_in[1];
    const int*   neigh2 = (const int*)d_in[2];
    const int*   ufi    = (const int*)d_in[3];
    const int*   ifi    = (const int*)d_in[4];
    const int*   uti    = (const int*)d_in[5];
    const int*   iti    = (const int*)d_in[6];
    const float* uide   = (const float*)d_in[7];
    const float* iide   = (const float*)d_in[8];
    const float* ufe    = (const float*)d_in[9];
    const float* ife    = (const float*)d_in[10];
    const float* wemb   = (const float*)d_in[11];
    const float* uw300  = (const float*)d_in[12];
    const float* iw300  = (const float*)d_in[13];
    const float* is768  = (const float*)d_in[14];
    const float* unum   = (const float*)d_in[15];
    const float* inum   = (const float*)d_in[16];
    const float* Wnu    = (const float*)d_in[17];
    const float* bnu    = (const float*)d_in[18];
    const float* Wni    = (const float*)d_in[19];
    const float* bni    = (const float*)d_in[20];
    const float* Wpu    = (const float*)d_in[21];
    const float* bpu    = (const float*)d_in[22];
    const float* Wpi    = (const float*)d_in[23];
    const float* bpi    = (const float*)d_in[24];
    const float* Ww     = (const float*)d_in[25];
    const float* bw     = (const float*)d_in[26];
    const float* Wv     = (const float*)d_in[27];
    const float* bv     = (const float*)d_in[28];
    float* out = (float*)d_out;

    float *px, *ph, *pfeu, *pfei, *pgs, *ptm, *pBu, *pBi;
    cudaGetSymbolAddress((void**)&px,   g_x);
    cudaGetSymbolAddress((void**)&ph,   g_h);
    cudaGetSymbolAddress((void**)&pfeu, g_pfe_u);
    cudaGetSymbolAddress((void**)&pfei, g_pfe_i);
    cudaGetSymbolAddress((void**)&pgs,  g_gs);
    cudaGetSymbolAddress((void**)&ptm,  g_tm);
    cudaGetSymbolAddress((void**)&pBu,  g_Bu);
    cudaGetSymbolAddress((void**)&pBi,  g_Bi);

    static const int SMEM_P = (4 * 128 * 36 + 4 * 32 * 72) * 4;    // 110592
    static const int SMEM_L = (2 * 128 * 68 + 16 * 72 + 128) * 4;
    cudaFuncSetAttribute(pgemm, cudaFuncAttributeMaxDynamicSharedMemorySize, SMEM_P);
    cudaFuncSetAttribute(layer_kernel<1>,
                         cudaFuncAttributeMaxDynamicSharedMemorySize, SMEM_L);
    cudaFuncSetAttribute(layer_kernel<0>,
                         cudaFuncAttributeMaxDynamicSharedMemorySize, SMEM_L);

    // ---- pack dense padded B matrices ----
    pack_kernel<<<(1248 * 64 + 255) / 256, 256>>>(Wpu, Wpi);

    // ---- feat table precompute: Pfe = 0.1 * feat_emb @ Wp[64:128] ----
    PArgs t{};
    t.Ar[0] = ufe; t.ab[0] = 0; t.ae[0] = 64; t.ars[0] = 64;
    for (int g = 1; g < 4; g++) { t.Ar[g] = ufe; t.ab[g] = 0; t.ae[g] = 0; t.ars[g] = 0; }
    t.B = Wpu + 64 * 64; t.gs = nullptr;
    t.out = pfeu; t.M = NFEAT; t.K = 64; t.scale = 0.1f;
    pgemm<<<(NFEAT + 127) / 128, 256, SMEM_P>>>(t);

    t.Ar[0] = ife; t.Ar[1] = ife; t.Ar[2] = ife; t.Ar[3] = ife;
    t.B = Wpi + 64 * 64; t.out = pfei;
    pgemm<<<(NFEAT + 127) / 128, 256, SMEM_P>>>(t);

    // ---- merged gather over all nodes ----
    gather_all<<<(N_NODEC * 32 + 255) / 256, 256>>>(
        ufi, ifi, uti, iti, unum, inum, Wnu, Wni,
        bpu, bnu, bpi, bni, pfeu, pfei, wemb, pgs, ptm);

    // ---- stage 1: x = dense([id | w300 | tm | s768]) @ B + gs ----
    PArgs u{};
    u.Ar[0] = uide;  u.ab[0] = 0;   u.ae[0] = 64;   u.ars[0] = 64;
    u.Ar[1] = uw300; u.ab[1] = 64;  u.ae[1] = 364;  u.ars[1] = 300;
    u.Ar[2] = ptm;   u.ab[2] = 368; u.ae[2] = 464;  u.ars[2] = 96;
    u.Ar[3] = uide;  u.ab[3] = 0;   u.ae[3] = 0;    u.ars[3] = 0;
    u.B = pBu; u.gs = pgs; u.out = px;
    u.M = N_USERC; u.K = 480; u.scale = 1.f;
    pgemm<<<(N_USERC + 127) / 128, 256, SMEM_P>>>(u);

    PArgs v{};
    v.Ar[0] = iide;  v.ab[0] = 0;   v.ae[0] = 64;   v.ars[0] = 64;
    v.Ar[1] = iw300; v.ab[1] = 64;  v.ae[1] = 364;  v.ars[1] = 300;
    v.Ar[2] = ptm + (size_t)N_USERC * 96;
                     v.ab[2] = 368; v.ae[2] = 464;  v.ars[2] = 96;
    v.Ar[3] = is768; v.ab[3] = 464; v.ae[3] = 1232; v.ars[3] = 768;
    v.B = pBi; v.gs = pgs + (size_t)N_USERC * 64;
    v.out = px + (size_t)N_USERC * 64;
    v.M = M_ITEMC; v.K = 1248; v.scale = 1.f;
    pgemm<<<(M_ITEMC + 127) / 128, 256, SMEM_P>>>(v);

    // ---- layer 0 (fused mean+agg+concat GEMM), relu ----
    layer_kernel<1><<<(MROWS + 127) / 128, 256, SMEM_L>>>(
        neigh2, neigh1, seeds, Wv, bv, Ww, bw, ph, MROWS, 1);

    // ---- layer 1, no relu, writes output ----
    layer_kernel<0><<<(BSEED + 127) / 128, 256, SMEM_L>>>(
        nullptr, nullptr, nullptr, Wv + 64 * 64, bv + 64,
        Ww + 128 * 64, bw + 64, out, BSEED, 0);
}

// round 8
// speedup vs baseline: 1.2683x; 1.2683x over previous
#include <cuda_runtime.h>
#include <cstdint>
#include <cstddef>

#define N_USERC 100000
#define M_ITEMC 50000
#define N_NODEC 150000
#define DD      64
#define BSEED   2048
#define SNB     20
#define M1ROWS  (BSEED*SNB)          // 40960
#define MROWS   (BSEED*SNB + BSEED)  // 43008
#define NFEAT   30000
#define VOCABC  20000

// ---------------- device scratch ----------
__device__ float g_x[(size_t)N_NODEC * DD];
__device__ float g_h[(size_t)MROWS * DD];
__device__ float g_pfe_u[(size_t)NFEAT * 64];
__device__ float g_pfe_i[(size_t)NFEAT * 64];
__device__ float g_pw_u[(size_t)VOCABC * 192];
__device__ float g_pw_i[(size_t)VOCABC * 192];
__device__ float g_gs[(size_t)N_NODEC * 64];
__device__ float g_Bu[(size_t)384 * 64];
__device__ float g_Bi[(size_t)1152 * 64];

__device__ __forceinline__ uint32_t f2tf(float v) {
    uint32_t r; asm("cvt.rna.tf32.f32 %0, %1;" : "=r"(r) : "f"(v)); return r;
}
__device__ __forceinline__ void mma_tf32(float c[4],
    uint32_t a0, uint32_t a1, uint32_t a2, uint32_t a3, uint32_t b0, uint32_t b1)
{
    asm volatile(
        "mma.sync.aligned.m16n8k8.row.col.f32.tf32.tf32.f32 "
        "{%0,%1,%2,%3},{%4,%5,%6,%7},{%8,%9},{%0,%1,%2,%3};"
        : "+f"(c[0]), "+f"(c[1]), "+f"(c[2]), "+f"(c[3])
        : "r"(a0), "r"(a1), "r"(a2), "r"(a3), "r"(b0), "r"(b1));
}
__device__ __forceinline__ uint32_t smem_u32(const void* p) {
    return (uint32_t)__cvta_generic_to_shared(p);
}
__device__ __forceinline__ void cp16(uint32_t dst, const void* src, int bytes) {
    asm volatile("cp.async.ca.shared.global [%0], [%1], 16, %2;\n"
                 :: "r"(dst), "l"(src), "r"(bytes));
}
__device__ __forceinline__ void cp_commit() {
    asm volatile("cp.async.commit_group;\n");
}
template<int N> __device__ __forceinline__ void cp_wait() {
    asm volatile("cp.async.wait_group %0;\n" :: "n"(N));
}

// =================== pipelined GEMM (R5 3-stage): out = scale*A@B (+gs) =====
struct PArgs {
    const float *A0, *A1, *A2;
    int a0e, a1b, a1e, a2b, a2e;
    int a0rs, a1rs, a2rs;
    const float* B;  long bsy;     // per-blockIdx.y B offset (floats)
    const float* gs;               // epilogue add [row*64+col] or null
    float* out; int ostride; long osy;
    int M, K; float scale;
};

__device__ __forceinline__ void compute32(float c[2][4][4],
    const float* Ad, const float* Bd, int wm, int wn, int lane)
{
    const int r0 = lane >> 2, q = lane & 3;
#pragma unroll
    for (int ks = 0; ks < 4; ks++) {
        const int kb = ks * 8;
        uint32_t a[2][4], b[4][2];
#pragma unroll
        for (int mi = 0; mi < 2; mi++) {
            int mr = wm * 32 + mi * 16 + r0;
            a[mi][0] = f2tf(Ad[mr * 36 + kb + q]);
            a[mi][1] = f2tf(Ad[(mr + 8) * 36 + kb + q]);
            a[mi][2] = f2tf(Ad[mr * 36 + kb + q + 4]);
            a[mi][3] = f2tf(Ad[(mr + 8) * 36 + kb + q + 4]);
        }
#pragma unroll
        for (int ni = 0; ni < 4; ni++) {
            int nc = wn * 32 + ni * 8 + r0;
            b[ni][0] = f2tf(Bd[(kb + q) * 72 + nc]);
            b[ni][1] = f2tf(Bd[(kb + q + 4) * 72 + nc]);
        }
#pragma unroll
        for (int mi = 0; mi < 2; mi++)
#pragma unroll
            for (int ni = 0; ni < 4; ni++)
                mma_tf32(c[mi][ni], a[mi][0], a[mi][1], a[mi][2], a[mi][3],
                         b[ni][0], b[ni][1]);
    }
}

__global__ void __launch_bounds__(256) pgemm(PArgs p)
{
    extern __shared__ float smp[];
    float* Asm = smp;                      // [3][128*36]
    float* Bsm = smp + 3 * 128 * 36;       // [3][32*72]

    const int tid = threadIdx.x, lane = tid & 31, wid = tid >> 5;
    const int wm = wid >> 1, wn = wid & 1;
    const int m0 = blockIdx.x * 128;
    const float* Bp = p.B + (size_t)blockIdx.y * p.bsy;

    auto issue = [&](int tile, int slot) {
        const int k0 = tile * 32;
        float* Ad = Asm + slot * (128 * 36);
        float* Bd = Bsm + slot * (32 * 72);
#pragma unroll
        for (int j = 0; j < 4; j++) {
            int ch = tid + j * 256;
            int r = ch >> 3, cq = ch & 7;
            int col = k0 + cq * 4;
            int row = m0 + r;
            const float* src = p.A0; int bytes = 0;
            if (row < p.M) {
                if (col < p.a0e) {
                    src = p.A0 + (size_t)row * p.a0rs + col; bytes = 16;
                } else if (col >= p.a1b && col < p.a1e) {
                    src = p.A1 + (size_t)row * p.a1rs + (col - p.a1b); bytes = 16;
                } else if (col >= p.a2b && col < p.a2e) {
                    src = p.A2 + (size_t)row * p.a2rs + (col - p.a2b); bytes = 16;
                }
            }
            cp16(smem_u32(Ad + r * 36 + cq * 4), src, bytes);
        }
#pragma unroll
        for (int j = 0; j < 2; j++) {
            int cb = tid + j * 256;
            int kr = cb >> 4, cq = cb & 15;
            cp16(smem_u32(Bd + kr * 72 + cq * 4),
                 Bp + (size_t)(k0 + kr) * 64 + cq * 4, 16);
        }
    };

    float c[2][4][4];
#pragma unroll
    for (int a = 0; a < 2; a++)
#pragma unroll
        for (int b = 0; b < 4; b++)
#pragma unroll
            for (int d = 0; d < 4; d++) c[a][b][d] = 0.f;

    const int nt = p.K / 32;
    issue(0, 0); cp_commit();
    if (nt > 1) { issue(1, 1); cp_commit(); }

    for (int t = 0; t < nt; t++) {
        if (t + 1 < nt) cp_wait<1>(); else cp_wait<0>();
        __syncthreads();
        if (t + 2 < nt) { issue(t + 2, (t + 2) % 3); cp_commit(); }
        const float* Ad = Asm + (t % 3) * (128 * 36);
        const float* Bd = Bsm + (t % 3) * (32 * 72);
        compute32(c, Ad, Bd, wm, wn, lane);
    }

    float* outp = p.out + (size_t)blockIdx.y * p.osy;
    const int r0 = lane >> 2, q = lane & 3;
#pragma unroll
    for (int mi = 0; mi < 2; mi++)
#pragma unroll
        for (int ni = 0; ni < 4; ni++) {
            int col = wn * 32 + ni * 8 + 2 * q;
            int row = m0 + wm * 32 + mi * 16 + r0;
#pragma unroll
            for (int h = 0; h < 2; h++) {
                int rr = row + h * 8;
                if (rr < p.M) {
                    float v0 = c[mi][ni][h * 2]     * p.scale;
                    float v1 = c[mi][ni][h * 2 + 1] * p.scale;
                    if (p.gs) {
                        float2 g = *reinterpret_cast<const float2*>(
                            p.gs + (size_t)rr * 64 + col);
                        v0 += g.x; v1 += g.y;
                    }
                    *reinterpret_cast<float2*>(outp + (size_t)rr * p.ostride + col) =
                        make_float2(v0, v1);
                }
            }
        }
}

// =================== pack padded dense B matrices ===========================
__global__ void pack_kernel(const float* __restrict__ Wpu,
                            const float* __restrict__ Wpi)
{
    int i = blockIdx.x * 256 + threadIdx.x;
    if (i < 384 * 64) {
        int r = i >> 6, n = i & 63; float v = 0.f;
        if (r < 64)       v = Wpu[(size_t)r * 64 + n];
        else if (r < 364) v = Wpu[(size_t)(r + 160) * 64 + n];
        g_Bu[i] = v;
    }
    if (i < 1152 * 64) {
        int r = i >> 6, n = i & 63; float v = 0.f;
        if (r < 64)                    v = Wpi[(size_t)r * 64 + n];
        else if (r < 364)              v = Wpi[(size_t)(r + 160) * 64 + n];
        else if (r >= 368 && r < 1136) v = Wpi[(size_t)(r + 156) * 64 + n];
        g_Bi[i] = v;
    }
}

// ========== gather kernel (4 nodes/warp, Wnum+bias in registers) ============
__global__ void __launch_bounds__(256) gather_kernel(
    const int* __restrict__ fi, const int* __restrict__ ti,
    const float* __restrict__ numer, const float* __restrict__ Wnum,
    const float* __restrict__ bproj, const float* __restrict__ bnum,
    const float* __restrict__ Pfe, const float* __restrict__ Pw,
    float* __restrict__ gs, int M)
{
    int warp = (blockIdx.x * blockDim.x + threadIdx.x) >> 5;
    int lane = threadIdx.x & 31;
    int base = warp * 4;
    if (base >= M) return;
    int c2 = lane * 2;

    // per-warp invariants in registers
    float2 wn[10];
#pragma unroll
    for (int d = 0; d < 10; d++)
        wn[d] = *reinterpret_cast<const float2*>(Wnum + (size_t)d * 64 + c2);
    float2 bias;
    bias.x = __ldg(bproj + c2)     + __ldg(bnum + c2);
    bias.y = __ldg(bproj + c2 + 1) + __ldg(bnum + c2 + 1);

#pragma unroll 1
    for (int k = 0; k < 4; k++) {
        int w = base + k;
        if (w >= M) break;
        float2 acc = bias;
#pragma unroll
        for (int d = 0; d < 10; d++) {
            float nv = __ldg(numer + (size_t)w * 10 + d);
            acc.x += nv * wn[d].x; acc.y += nv * wn[d].y;
        }
#pragma unroll
        for (int j = 0; j < 10; j++) {
            int ix = __ldg(fi + (size_t)w * 10 + j);
            float2 v = *reinterpret_cast<const float2*>(Pfe + (size_t)ix * 64 + c2);
            acc.x += v.x; acc.y += v.y;
        }
#pragma unroll
        for (int s = 0; s < 3; s++) {
            const int* tb = ti + (size_t)w * 24 + s * 8;
#pragma unroll
            for (int t = 0; t < 8; t++) {
                int ix = __ldg(tb + t);
                float2 v = *reinterpret_cast<const float2*>(
                    Pw + (size_t)ix * 192 + s * 64 + c2);
                acc.x += v.x; acc.y += v.y;
            }
        }
        *reinterpret_cast<float2*>(gs + (size_t)w * 64 + c2) = acc;
    }
}

// =================== fused SAGE layer ======================================
__device__ __forceinline__ void compute_tile68(float c[2][4][4],
    const uint32_t (*Asrc)[68], int kbase, const uint32_t (*Bs)[72],
    int wm, int wn, int lane)
{
    const int r0 = lane >> 2, q = lane & 3;
#pragma unroll
    for (int ks = 0; ks < 2; ks++) {
        const int kb = ks * 8;
        uint32_t a[2][4], b[4][2];
#pragma unroll
        for (int mi = 0; mi < 2; mi++) {
            int mr = wm * 32 + mi * 16 + r0;
            a[mi][0] = Asrc[mr][kbase + kb + q];
            a[mi][1] = Asrc[mr + 8][kbase + kb + q];
            a[mi][2] = Asrc[mr][kbase + kb + q + 4];
            a[mi][3] = Asrc[mr + 8][kbase + kb + q + 4];
        }
#pragma unroll
        for (int ni = 0; ni < 4; ni++) {
            int nc = wn * 32 + ni * 8 + r0;
            b[ni][0] = Bs[kb + q][nc];
            b[ni][1] = Bs[kb + q + 4][nc];
        }
#pragma unroll
        for (int mi = 0; mi < 2; mi++)
#pragma unroll
            for (int ni = 0; ni < 4; ni++)
                mma_tf32(c[mi][ni], a[mi][0], a[mi][1], a[mi][2], a[mi][3],
                         b[ni][0], b[ni][1]);
    }
}

template<int L0>
__global__ void __launch_bounds__(256) layer_kernel(
    const int* __restrict__ neigh2, const int* __restrict__ neigh1,
    const int* __restrict__ seeds,
    const float* __restrict__ Wv, const float* __restrict__ bv,
    const float* __restrict__ Ww, const float* __restrict__ bw,
    float* __restrict__ outp, int M, int relu)
{
    extern __shared__ uint32_t dsm[];
    uint32_t (*Ms)[68] = (uint32_t(*)[68])dsm;
    uint32_t (*Ss)[68] = (uint32_t(*)[68])(dsm + 128 * 68);
    uint32_t (*Bs)[72] = (uint32_t(*)[72])(dsm + 2 * 128 * 68);
    float* sbv = (float*)(dsm + 2 * 128 * 68 + 16 * 72);
    float* sbw = sbv + 64;

    const int tid = threadIdx.x, lane = tid & 31, wid = tid >> 5;
    const int wm = wid >> 1, wn = wid & 1;
    const int m0 = blockIdx.x * 128;

    if (tid < 64) { sbv[tid] = bv[tid]; sbw[tid] = bw[tid]; }

#pragma unroll 1
    for (int rr = 0; rr < 16; ++rr) {
        int ln = wid * 16 + rr;
        int r = m0 + ln;
        float ax = 0.f, ay = 0.f;
        float2 self = make_float2(0.f, 0.f);
        if (r < M) {
            if (L0) {
                const int* idx = (r < M1ROWS) ? (neigh2 + (size_t)r * SNB)
                                              : (neigh1 + (size_t)(r - M1ROWS) * SNB);
#pragma unroll
                for (int j = 0; j < SNB; j++) {
                    int n = __ldg(idx + j);
                    float2 v = *reinterpret_cast<const float2*>(g_x + (size_t)n * 64 + lane * 2);
                    ax += v.x; ay += v.y;
                }
                int sn = (r < M1ROWS) ? __ldg(neigh1 + r) : __ldg(seeds + r - M1ROWS);
                self = *reinterpret_cast<const float2*>(g_x + (size_t)sn * 64 + lane * 2);
            } else {
#pragma unroll
                for (int j = 0; j < SNB; j++) {
                    float2 v = *reinterpret_cast<const float2*>(
                        g_h + (size_t)(r * SNB + j) * 64 + lane * 2);
                    ax += v.x; ay += v.y;
                }
                self = *reinterpret_cast<const float2*>(
                    g_h + (size_t)(M1ROWS + r) * 64 + lane * 2);
            }
            ax *= 0.05f; ay *= 0.05f;
        }
        Ms[ln][lane * 2]     = f2tf(ax);
        Ms[ln][lane * 2 + 1] = f2tf(ay);
        Ss[ln][lane * 2]     = f2tf(self.x);
        Ss[ln][lane * 2 + 1] = f2tf(self.y);
    }

    float ca[2][4][4];
#pragma unroll
    for (int a = 0; a < 2; a++)
#pragma unroll
        for (int b = 0; b < 4; b++)
#pragma unroll
            for (int d = 0; d < 4; d++) ca[a][b][d] = 0.f;

    for (int k0 = 0; k0 < 64; k0 += 16) {
        __syncthreads();
        for (int i = tid; i < 16 * 64; i += 256) {
            int kk = i >> 6, n = i & 63;
            Bs[kk][n] = f2tf(Wv[(size_t)(k0 + kk) * 64 + n]);
        }
        __syncthreads();
        compute_tile68(ca, Ms, k0, Bs, wm, wn, lane);
    }
    __syncthreads();

    {
        const int r0 = lane >> 2, q = lane & 3;
#pragma unroll
        for (int mi = 0; mi < 2; mi++)
#pragma unroll
            for (int ni = 0; ni < 4; ni++) {
                int col = wn * 32 + ni * 8 + 2 * q;
                int lr = wm * 32 + mi * 16 + r0;
#pragma unroll
                for (int h = 0; h < 2; h++) {
                    int lrow = lr + h * 8;
                    Ms[lrow][col]     = f2tf(ca[mi][ni][h * 2]     + sbv[col]);
                    Ms[lrow][col + 1] = f2tf(ca[mi][ni][h * 2 + 1] + sbv[col + 1]);
                }
            }
    }
    __syncthreads();

    float ch[2][4][4];
#pragma unroll
    for (int a = 0; a < 2; a++)
#pragma unroll
        for (int b = 0; b < 4; b++)
#pragma unroll
            for (int d = 0; d < 4; d++) ch[a][b][d] = 0.f;

    for (int k0 = 0; k0 < 128; k0 += 16) {
        __syncthreads();
        for (int i = tid; i < 16 * 64; i += 256) {
            int kk = i >> 6, n = i & 63;
            Bs[kk][n] = f2tf(Ww[(size_t)(k0 + kk) * 64 + n]);
        }
        __syncthreads();
        if (k0 < 64) compute_tile68(ch, Ss, k0,      Bs, wm, wn, lane);
        else         compute_tile68(ch, Ms, k0 - 64, Bs, wm, wn, lane);
    }

    const int r0 = lane >> 2, q = lane & 3;
#pragma unroll
    for (int mi = 0; mi < 2; mi++)
#pragma unroll
        for (int ni = 0; ni < 4; ni++) {
            int col = wn * 32 + ni * 8 + 2 * q;
            int row = m0 + wm * 32 + mi * 16 + r0;
#pragma unroll
            for (int h = 0; h < 2; h++) {
                int rr = row + h * 8;
                if (rr < M) {
                    float v0 = ch[mi][ni][h * 2]     + sbw[col];
                    float v1 = ch[mi][ni][h * 2 + 1] + sbw[col + 1];
                    if (relu) { v0 = fmaxf(v0, 0.f); v1 = fmaxf(v1, 0.f); }
                    *reinterpret_cast<float2*>(outp + (size_t)rr * 64 + col) =
                        make_float2(v0, v1);
                }
            }
        }
}

// ============================ launch =========================================
extern "C" void kernel_launch(void* const* d_in, const int* in_sizes, int n_in,
                              void* d_out, int out_size)
{
    const int*   seeds  = (const int*)d_in[0];
    const int*   neigh1 = (const int*)d_in[1];
    const int*   neigh2 = (const int*)d_in[2];
    const int*   ufi    = (const int*)d_in[3];
    const int*   ifi    = (const int*)d_in[4];
    const int*   uti    = (const int*)d_in[5];
    const int*   iti    = (const int*)d_in[6];
    const float* uide   = (const float*)d_in[7];
    const float* iide   = (const float*)d_in[8];
    const float* ufe    = (const float*)d_in[9];
    const float* ife    = (const float*)d_in[10];
    const float* wemb   = (const float*)d_in[11];
    const float* uw300  = (const float*)d_in[12];
    const float* iw300  = (const float*)d_in[13];
    const float* is768  = (const float*)d_in[14];
    const float* unum   = (const float*)d_in[15];
    const float* inum   = (const float*)d_in[16];
    const float* Wnu    = (const float*)d_in[17];
    const float* bnu    = (const float*)d_in[18];
    const float* Wni    = (const float*)d_in[19];
    const float* bni    = (const float*)d_in[20];
    const float* Wpu    = (const float*)d_in[21];
    const float* bpu    = (const float*)d_in[22];
    const float* Wpi    = (const float*)d_in[23];
    const float* bpi    = (const float*)d_in[24];
    const float* Ww     = (const float*)d_in[25];
    const float* bw     = (const float*)d_in[26];
    const float* Wv     = (const float*)d_in[27];
    const float* bv     = (const float*)d_in[28];
    float* out = (float*)d_out;

    float *px, *ph, *pfeu, *pfei, *pwu, *pwi, *pgs, *pBu, *pBi;
    cudaGetSymbolAddress((void**)&px,   g_x);
    cudaGetSymbolAddress((void**)&ph,   g_h);
    cudaGetSymbolAddress((void**)&pfeu, g_pfe_u);
    cudaGetSymbolAddress((void**)&pfei, g_pfe_i);
    cudaGetSymbolAddress((void**)&pwu,  g_pw_u);
    cudaGetSymbolAddress((void**)&pwi,  g_pw_i);
    cudaGetSymbolAddress((void**)&pgs,  g_gs);
    cudaGetSymbolAddress((void**)&pBu,  g_Bu);
    cudaGetSymbolAddress((void**)&pBi,  g_Bi);

    static const int SMEM_P = (3 * 128 * 36 + 3 * 32 * 72) * 4;    // 82944
    static const int SMEM_L = (2 * 128 * 68 + 16 * 72 + 128) * 4;
    cudaFuncSetAttribute(pgemm, cudaFuncAttributeMaxDynamicSharedMemorySize, SMEM_P);
    cudaFuncSetAttribute(layer_kernel<1>,
                         cudaFuncAttributeMaxDynamicSharedMemorySize, SMEM_L);
    cudaFuncSetAttribute(layer_kernel<0>,
                         cudaFuncAttributeMaxDynamicSharedMemorySize, SMEM_L);

    // ---- pack dense padded B matrices ----
    pack_kernel<<<(1152 * 64 + 255) / 256, 256>>>(Wpu, Wpi);

    // ---- table precompute ----
    PArgs t{};
    t.A0 = ufe; t.a0e = 64; t.a0rs = 64;
    t.a1b = 0; t.a1e = 0; t.a2b = 0; t.a2e = 0; t.A1 = ufe; t.A2 = ufe;
    t.B = Wpu + 64 * 64; t.bsy = 0; t.gs = nullptr;
    t.out = pfeu; t.ostride = 64; t.osy = 0;
    t.M = NFEAT; t.K = 64; t.scale = 0.1f;
    pgemm<<<dim3((NFEAT + 127) / 128, 1), 256, SMEM_P>>>(t);

    t.A0 = ife; t.A1 = ife; t.A2 = ife; t.B = Wpi + 64 * 64; t.out = pfei;
    pgemm<<<dim3((NFEAT + 127) / 128, 1), 256, SMEM_P>>>(t);

    t.A0 = wemb; t.A1 = wemb; t.A2 = wemb; t.a0e = 32; t.a0rs = 32;
    t.B = Wpu + 128 * 64; t.bsy = 32 * 64;
    t.out = pwu; t.ostride = 192; t.osy = 64;
    t.M = VOCABC; t.K = 32; t.scale = 0.125f;
    pgemm<<<dim3((VOCABC + 127) / 128, 3), 256, SMEM_P>>>(t);

    t.B = Wpi + 128 * 64; t.out = pwi;
    pgemm<<<dim3((VOCABC + 127) / 128, 3), 256, SMEM_P>>>(t);

    // ---- gather: gs = bias + numeric@Wnum + feat + text (4 nodes/warp) ----
    {
        int warps_u = (N_USERC + 3) / 4;
        int warps_i = (M_ITEMC + 3) / 4;
        gather_kernel<<<(warps_u * 32 + 255) / 256, 256>>>(
            ufi, uti, unum, Wnu, bpu, bnu, pfeu, pwu, pgs, N_USERC);
        gather_kernel<<<(warps_i * 32 + 255) / 256, 256>>>(
            ifi, iti, inum, Wni, bpi, bni, pfei, pwi,
            pgs + (size_t)N_USERC * 64, M_ITEMC);
    }

    // ---- stage 1: x = dense(A) @ B + gs ----
    PArgs u{};
    u.A0 = uide; u.a0e = 64;  u.a0rs = 64;
    u.A1 = uw300; u.a1b = 64; u.a1e = 364; u.a1rs = 300;
    u.A2 = uide; u.a2b = 0; u.a2e = 0; u.a2rs = 0;
    u.B = pBu; u.bsy = 0; u.gs = pgs;
    u.out = px; u.ostride = 64; u.osy = 0;
    u.M = N_USERC; u.K = 384; u.scale = 1.f;
    pgemm<<<dim3((N_USERC + 127) / 128, 1), 256, SMEM_P>>>(u);

    PArgs v{};
    v.A0 = iide; v.a0e = 64;  v.a0rs = 64;
    v.A1 = iw300; v.a1b = 64; v.a1e = 364; v.a1rs = 300;
    v.A2 = is768; v.a2b = 368; v.a2e = 1136; v.a2rs = 768;
    v.B = pBi; v.bsy = 0; v.gs = pgs + (size_t)N_USERC * 64;
    v.out = px + (size_t)N_USERC * 64; v.ostride = 64; v.osy = 0;
    v.M = M_ITEMC; v.K = 1152; v.scale = 1.f;
    pgemm<<<dim3((M_ITEMC + 127) / 128, 1), 256, SMEM_P>>>(v);

    // ---- layer 0 (fused mean+agg+concat GEMM), relu ----
    layer_kernel<1><<<(MROWS + 127) / 128, 256, SMEM_L>>>(
        neigh2, neigh1, seeds, Wv, bv, Ww, bw, ph, MROWS, 1);

    // ---- layer 1, no relu, writes output ----
    layer_kernel<0><<<(BSEED + 127) / 128, 256, SMEM_L>>>(
        nullptr, nullptr, nullptr, Wv + 64 * 64, bv + 64,
        Ww + 128 * 64, bw + 64, out, BSEED, 0);
}

// round 9
// speedup vs baseline: 1.5074x; 1.1886x over previous
#include <cuda_runtime.h>
#include <cstdint>
#include <cstddef>

#define N_USERC 100000
#define M_ITEMC 50000
#define N_NODEC 150000
#define DD      64
#define BSEED   2048
#define SNB     20
#define M1ROWS  (BSEED*SNB)          // 40960
#define MROWS   (BSEED*SNB + BSEED)  // 43008
#define NFEAT   30000
#define VOCABC  20000

// ---------------- device scratch ----------
__device__ float g_x[(size_t)N_NODEC * DD];
__device__ float g_h[(size_t)MROWS * DD];
__device__ float g_pfe_u[(size_t)NFEAT * 64];
__device__ float g_pfe_i[(size_t)NFEAT * 64];
__device__ float g_pw_u[(size_t)VOCABC * 192];
__device__ float g_pw_i[(size_t)VOCABC * 192];
__device__ float g_gs[(size_t)N_NODEC * 64];
__device__ float g_Bu[(size_t)384 * 64];
__device__ float g_Bi[(size_t)1152 * 64];

__device__ __forceinline__ uint32_t f2tf(float v) {
    uint32_t r; asm("cvt.rna.tf32.f32 %0, %1;" : "=r"(r) : "f"(v)); return r;
}
__device__ __forceinline__ void mma_tf32(float c[4],
    uint32_t a0, uint32_t a1, uint32_t a2, uint32_t a3, uint32_t b0, uint32_t b1)
{
    asm volatile(
        "mma.sync.aligned.m16n8k8.row.col.f32.tf32.tf32.f32 "
        "{%0,%1,%2,%3},{%4,%5,%6,%7},{%8,%9},{%0,%1,%2,%3};"
        : "+f"(c[0]), "+f"(c[1]), "+f"(c[2]), "+f"(c[3])
        : "r"(a0), "r"(a1), "r"(a2), "r"(a3), "r"(b0), "r"(b1));
}
__device__ __forceinline__ uint32_t smem_u32(const void* p) {
    return (uint32_t)__cvta_generic_to_shared(p);
}
__device__ __forceinline__ void cp16(uint32_t dst, const void* src, int bytes) {
    asm volatile("cp.async.ca.shared.global [%0], [%1], 16, %2;\n"
                 :: "r"(dst), "l"(src), "r"(bytes));
}
__device__ __forceinline__ void cp_commit() {
    asm volatile("cp.async.commit_group;\n");
}
template<int N> __device__ __forceinline__ void cp_wait() {
    asm volatile("cp.async.wait_group %0;\n" :: "n"(N));
}

// =================== pipelined GEMM (R5 3-stage): out = scale*A@B (+gs) =====
struct PArgs {
    const float *A0, *A1, *A2;
    int a0e, a1b, a1e, a2b, a2e;
    int a0rs, a1rs, a2rs;
    const float* B;  long bsy;
    const float* gs;
    float* out; int ostride; long osy;
    int M, K; float scale;
};

__device__ __forceinline__ void compute32(float c[2][4][4],
    const float* Ad, const float* Bd, int wm, int wn, int lane)
{
    const int r0 = lane >> 2, q = lane & 3;
#pragma unroll
    for (int ks = 0; ks < 4; ks++) {
        const int kb = ks * 8;
        uint32_t a[2][4], b[4][2];
#pragma unroll
        for (int mi = 0; mi < 2; mi++) {
            int mr = wm * 32 + mi * 16 + r0;
            a[mi][0] = f2tf(Ad[mr * 36 + kb + q]);
            a[mi][1] = f2tf(Ad[(mr + 8) * 36 + kb + q]);
            a[mi][2] = f2tf(Ad[mr * 36 + kb + q + 4]);
            a[mi][3] = f2tf(Ad[(mr + 8) * 36 + kb + q + 4]);
        }
#pragma unroll
        for (int ni = 0; ni < 4; ni++) {
            int nc = wn * 32 + ni * 8 + r0;
            b[ni][0] = f2tf(Bd[(kb + q) * 72 + nc]);
            b[ni][1] = f2tf(Bd[(kb + q + 4) * 72 + nc]);
        }
#pragma unroll
        for (int mi = 0; mi < 2; mi++)
#pragma unroll
            for (int ni = 0; ni < 4; ni++)
                mma_tf32(c[mi][ni], a[mi][0], a[mi][1], a[mi][2], a[mi][3],
                         b[ni][0], b[ni][1]);
    }
}

__global__ void __launch_bounds__(256) pgemm(PArgs p)
{
    extern __shared__ float smp[];
    float* Asm = smp;                      // [3][128*36]
    float* Bsm = smp + 3 * 128 * 36;       // [3][32*72]

    const int tid = threadIdx.x, lane = tid & 31, wid = tid >> 5;
    const int wm = wid >> 1, wn = wid & 1;
    const int m0 = blockIdx.x * 128;
    const float* Bp = p.B + (size_t)blockIdx.y * p.bsy;

    auto issue = [&](int tile, int slot) {
        const int k0 = tile * 32;
        float* Ad = Asm + slot * (128 * 36);
        float* Bd = Bsm + slot * (32 * 72);
#pragma unroll
        for (int j = 0; j < 4; j++) {
            int ch = tid + j * 256;
            int r = ch >> 3, cq = ch & 7;
            int col = k0 + cq * 4;
            int row = m0 + r;
            const float* src = p.A0; int bytes = 0;
            if (row < p.M) {
                if (col < p.a0e) {
                    src = p.A0 + (size_t)row * p.a0rs + col; bytes = 16;
                } else if (col >= p.a1b && col < p.a1e) {
                    src = p.A1 + (size_t)row * p.a1rs + (col - p.a1b); bytes = 16;
                } else if (col >= p.a2b && col < p.a2e) {
                    src = p.A2 + (size_t)row * p.a2rs + (col - p.a2b); bytes = 16;
                }
            }
            cp16(smem_u32(Ad + r * 36 + cq * 4), src, bytes);
        }
#pragma unroll
        for (int j = 0; j < 2; j++) {
            int cb = tid + j * 256;
            int kr = cb >> 4, cq = cb & 15;
            cp16(smem_u32(Bd + kr * 72 + cq * 4),
                 Bp + (size_t)(k0 + kr) * 64 + cq * 4, 16);
        }
    };

    float c[2][4][4];
#pragma unroll
    for (int a = 0; a < 2; a++)
#pragma unroll
        for (int b = 0; b < 4; b++)
#pragma unroll
            for (int d = 0; d < 4; d++) c[a][b][d] = 0.f;

    const int nt = p.K / 32;
    issue(0, 0); cp_commit();
    if (nt > 1) { issue(1, 1); cp_commit(); }

    for (int t = 0; t < nt; t++) {
        if (t + 1 < nt) cp_wait<1>(); else cp_wait<0>();
        __syncthreads();
        if (t + 2 < nt) { issue(t + 2, (t + 2) % 3); cp_commit(); }
        const float* Ad = Asm + (t % 3) * (128 * 36);
        const float* Bd = Bsm + (t % 3) * (32 * 72);
        compute32(c, Ad, Bd, wm, wn, lane);
    }

    float* outp = p.out + (size_t)blockIdx.y * p.osy;
    const int r0 = lane >> 2, q = lane & 3;
#pragma unroll
    for (int mi = 0; mi < 2; mi++)
#pragma unroll
        for (int ni = 0; ni < 4; ni++) {
            int col = wn * 32 + ni * 8 + 2 * q;
            int row = m0 + wm * 32 + mi * 16 + r0;
#pragma unroll
            for (int h = 0; h < 2; h++) {
                int rr = row + h * 8;
                if (rr < p.M) {
                    float v0 = c[mi][ni][h * 2]     * p.scale;
                    float v1 = c[mi][ni][h * 2 + 1] * p.scale;
                    if (p.gs) {
                        float2 g = *reinterpret_cast<const float2*>(
                            p.gs + (size_t)rr * 64 + col);
                        v0 += g.x; v1 += g.y;
                    }
                    *reinterpret_cast<float2*>(outp + (size_t)rr * p.ostride + col) =
                        make_float2(v0, v1);
                }
            }
        }
}

// =================== pack padded dense B matrices ===========================
__global__ void pack_kernel(const float* __restrict__ Wpu,
                            const float* __restrict__ Wpi)
{
    int i = blockIdx.x * 256 + threadIdx.x;
    if (i < 384 * 64) {
        int r = i >> 6, n = i & 63; float v = 0.f;
        if (r < 64)       v = Wpu[(size_t)r * 64 + n];
        else if (r < 364) v = Wpu[(size_t)(r + 160) * 64 + n];
        g_Bu[i] = v;
    }
    if (i < 1152 * 64) {
        int r = i >> 6, n = i & 63; float v = 0.f;
        if (r < 64)                    v = Wpi[(size_t)r * 64 + n];
        else if (r < 364)              v = Wpi[(size_t)(r + 160) * 64 + n];
        else if (r >= 368 && r < 1136) v = Wpi[(size_t)(r + 156) * 64 + n];
        g_Bi[i] = v;
    }
}

// ========== gather kernel (R5: warp per node) ================================
__global__ void __launch_bounds__(256) gather_kernel(
    const int* __restrict__ fi, const int* __restrict__ ti,
    const float* __restrict__ numer, const float* __restrict__ Wnum,
    const float* __restrict__ bproj, const float* __restrict__ bnum,
    const float* __restrict__ Pfe, const float* __restrict__ Pw,
    float* __restrict__ gs, int M)
{
    int w = (blockIdx.x * blockDim.x + threadIdx.x) >> 5;
    int lane = threadIdx.x & 31;
    if (w >= M) return;
    int c2 = lane * 2;

    float2 acc;
    acc.x = __ldg(bproj + c2)     + __ldg(bnum + c2);
    acc.y = __ldg(bproj + c2 + 1) + __ldg(bnum + c2 + 1);

#pragma unroll
    for (int d = 0; d < 10; d++) {
        float nv = __ldg(numer + (size_t)w * 10 + d);
        float2 ww = *reinterpret_cast<const float2*>(Wnum + (size_t)d * 64 + c2);
        acc.x += nv * ww.x; acc.y += nv * ww.y;
    }
#pragma unroll
    for (int j = 0; j < 10; j++) {
        int ix = __ldg(fi + (size_t)w * 10 + j);
        float2 v = *reinterpret_cast<const float2*>(Pfe + (size_t)ix * 64 + c2);
        acc.x += v.x; acc.y += v.y;
    }
#pragma unroll
    for (int s = 0; s < 3; s++) {
#pragma unroll
        for (int t = 0; t < 8; t++) {
            int ix = __ldg(ti + (size_t)w * 24 + s * 8 + t);
            float2 v = *reinterpret_cast<const float2*>(
                Pw + (size_t)ix * 192 + s * 64 + c2);
            acc.x += v.x; acc.y += v.y;
        }
    }
    *reinterpret_cast<float2*>(gs + (size_t)w * 64 + c2) = acc;
}

// =================== fused SAGE layer ======================================
__device__ __forceinline__ void compute_tile68(float c[2][4][4],
    const uint32_t (*Asrc)[68], int kbase, const uint32_t (*Bs)[72],
    int wm, int wn, int lane)
{
    const int r0 = lane >> 2, q = lane & 3;
#pragma unroll
    for (int ks = 0; ks < 2; ks++) {
        const int kb = ks * 8;
        uint32_t a[2][4], b[4][2];
#pragma unroll
        for (int mi = 0; mi < 2; mi++) {
            int mr = wm * 32 + mi * 16 + r0;
            a[mi][0] = Asrc[mr][kbase + kb + q];
            a[mi][1] = Asrc[mr + 8][kbase + kb + q];
            a[mi][2] = Asrc[mr][kbase + kb + q + 4];
            a[mi][3] = Asrc[mr + 8][kbase + kb + q + 4];
        }
#pragma unroll
        for (int ni = 0; ni < 4; ni++) {
            int nc = wn * 32 + ni * 8 + r0;
            b[ni][0] = Bs[kb + q][nc];
            b[ni][1] = Bs[kb + q + 4][nc];
        }
#pragma unroll
        for (int mi = 0; mi < 2; mi++)
#pragma unroll
            for (int ni = 0; ni < 4; ni++)
                mma_tf32(c[mi][ni], a[mi][0], a[mi][1], a[mi][2], a[mi][3],
                         b[ni][0], b[ni][1]);
    }
}

template<int L0>
__global__ void __launch_bounds__(256) layer_kernel(
    const int* __restrict__ neigh2, const int* __restrict__ neigh1,
    const int* __restrict__ seeds,
    const float* __restrict__ Wv, const float* __restrict__ bv,
    const float* __restrict__ Ww, const float* __restrict__ bw,
    float* __restrict__ outp, int M, int relu)
{
    extern __shared__ uint32_t dsm[];
    uint32_t (*Ms)[68] = (uint32_t(*)[68])dsm;
    uint32_t (*Ss)[68] = (uint32_t(*)[68])(dsm + 128 * 68);
    uint32_t (*Bs)[72] = (uint32_t(*)[72])(dsm + 2 * 128 * 68);
    float* sbv = (float*)(dsm + 2 * 128 * 68 + 16 * 72);
    float* sbw = sbv + 64;

    const int tid = threadIdx.x, lane = tid & 31, wid = tid >> 5;
    const int wm = wid >> 1, wn = wid & 1;
    const int m0 = blockIdx.x * 128;

    if (tid < 64) { sbv[tid] = bv[tid]; sbw[tid] = bw[tid]; }

#pragma unroll 1
    for (int rr = 0; rr < 16; ++rr) {
        int ln = wid * 16 + rr;
        int r = m0 + ln;
        float ax = 0.f, ay = 0.f;
        float2 self = make_float2(0.f, 0.f);
        if (r < M) {
            if (L0) {
                const int* idx = (r < M1ROWS) ? (neigh2 + (size_t)r * SNB)
                                              : (neigh1 + (size_t)(r - M1ROWS) * SNB);
#pragma unroll
                for (int j = 0; j < SNB; j++) {
                    int n = __ldg(idx + j);
                    float2 v = *reinterpret_cast<const float2*>(g_x + (size_t)n * 64 + lane * 2);
                    ax += v.x; ay += v.y;
                }
                int sn = (r < M1ROWS) ? __ldg(neigh1 + r) : __ldg(seeds + r - M1ROWS);
                self = *reinterpret_cast<const float2*>(g_x + (size_t)sn * 64 + lane * 2);
            } else {
#pragma unroll
                for (int j = 0; j < SNB; j++) {
                    float2 v = *reinterpret_cast<const float2*>(
                        g_h + (size_t)(r * SNB + j) * 64 + lane * 2);
                    ax += v.x; ay += v.y;
                }
                self = *reinterpret_cast<const float2*>(
                    g_h + (size_t)(M1ROWS + r) * 64 + lane * 2);
            }
            ax *= 0.05f; ay *= 0.05f;
        }
        Ms[ln][lane * 2]     = f2tf(ax);
        Ms[ln][lane * 2 + 1] = f2tf(ay);
        Ss[ln][lane * 2]     = f2tf(self.x);
        Ss[ln][lane * 2 + 1] = f2tf(self.y);
    }

    float ca[2][4][4];
#pragma unroll
    for (int a = 0; a < 2; a++)
#pragma unroll
        for (int b = 0; b < 4; b++)
#pragma unroll
            for (int d = 0; d < 4; d++) ca[a][b][d] = 0.f;

    for (int k0 = 0; k0 < 64; k0 += 16) {
        __syncthreads();
        for (int i = tid; i < 16 * 64; i += 256) {
            int kk = i >> 6, n = i & 63;
            Bs[kk][n] = f2tf(Wv[(size_t)(k0 + kk) * 64 + n]);
        }
        __syncthreads();
        compute_tile68(ca, Ms, k0, Bs, wm, wn, lane);
    }
    __syncthreads();

    {
        const int r0 = lane >> 2, q = lane & 3;
#pragma unroll
        for (int mi = 0; mi < 2; mi++)
#pragma unroll
            for (int ni = 0; ni < 4; ni++) {
                int col = wn * 32 + ni * 8 + 2 * q;
                int lr = wm * 32 + mi * 16 + r0;
#pragma unroll
                for (int h = 0; h < 2; h++) {
                    int lrow = lr + h * 8;
                    Ms[lrow][col]     = f2tf(ca[mi][ni][h * 2]     + sbv[col]);
                    Ms[lrow][col + 1] = f2tf(ca[mi][ni][h * 2 + 1] + sbv[col + 1]);
                }
            }
    }
    __syncthreads();

    float ch[2][4][4];
#pragma unroll
    for (int a = 0; a < 2; a++)
#pragma unroll
        for (int b = 0; b < 4; b++)
#pragma unroll
            for (int d = 0; d < 4; d++) ch[a][b][d] = 0.f;

    for (int k0 = 0; k0 < 128; k0 += 16) {
        __syncthreads();
        for (int i = tid; i < 16 * 64; i += 256) {
            int kk = i >> 6, n = i & 63;
            Bs[kk][n] = f2tf(Ww[(size_t)(k0 + kk) * 64 + n]);
        }
        __syncthreads();
        if (k0 < 64) compute_tile68(ch, Ss, k0,      Bs, wm, wn, lane);
        else         compute_tile68(ch, Ms, k0 - 64, Bs, wm, wn, lane);
    }

    const int r0 = lane >> 2, q = lane & 3;
#pragma unroll
    for (int mi = 0; mi < 2; mi++)
#pragma unroll
        for (int ni = 0; ni < 4; ni++) {
            int col = wn * 32 + ni * 8 + 2 * q;
            int row = m0 + wm * 32 + mi * 16 + r0;
#pragma unroll
            for (int h = 0; h < 2; h++) {
                int rr = row + h * 8;
                if (rr < M) {
                    float v0 = ch[mi][ni][h * 2]     + sbw[col];
                    float v1 = ch[mi][ni][h * 2 + 1] + sbw[col + 1];
                    if (relu) { v0 = fmaxf(v0, 0.f); v1 = fmaxf(v1, 0.f); }
                    *reinterpret_cast<float2*>(outp + (size_t)rr * 64 + col) =
                        make_float2(v0, v1);
                }
            }
        }
}

// ============================ launch =========================================
extern "C" void kernel_launch(void* const* d_in, const int* in_sizes, int n_in,
                              void* d_out, int out_size)
{
    const int*   seeds  = (const int*)d_in[0];
    const int*   neigh1 = (const int*)d_in[1];
    const int*   neigh2 = (const int*)d_in[2];
    const int*   ufi    = (const int*)d_in[3];
    const int*   ifi    = (const int*)d_in[4];
    const int*   uti    = (const int*)d_in[5];
    const int*   iti    = (const int*)d_in[6];
    const float* uide   = (const float*)d_in[7];
    const float* iide   = (const float*)d_in[8];
    const float* ufe    = (const float*)d_in[9];
    const float* ife    = (const float*)d_in[10];
    const float* wemb   = (const float*)d_in[11];
    const float* uw300  = (const float*)d_in[12];
    const float* iw300  = (const float*)d_in[13];
    const float* is768  = (const float*)d_in[14];
    const float* unum   = (const float*)d_in[15];
    const float* inum   = (const float*)d_in[16];
    const float* Wnu    = (const float*)d_in[17];
    const float* bnu    = (const float*)d_in[18];
    const float* Wni    = (const float*)d_in[19];
    const float* bni    = (const float*)d_in[20];
    const float* Wpu    = (const float*)d_in[21];
    const float* bpu    = (const float*)d_in[22];
    const float* Wpi    = (const float*)d_in[23];
    const float* bpi    = (const float*)d_in[24];
    const float* Ww     = (const float*)d_in[25];
    const float* bw     = (const float*)d_in[26];
    const float* Wv     = (const float*)d_in[27];
    const float* bv     = (const float*)d_in[28];
    float* out = (float*)d_out;

    float *px, *ph, *pfeu, *pfei, *pwu, *pwi, *pgs, *pBu, *pBi;
    cudaGetSymbolAddress((void**)&px,   g_x);
    cudaGetSymbolAddress((void**)&ph,   g_h);
    cudaGetSymbolAddress((void**)&pfeu, g_pfe_u);
    cudaGetSymbolAddress((void**)&pfei, g_pfe_i);
    cudaGetSymbolAddress((void**)&pwu,  g_pw_u);
    cudaGetSymbolAddress((void**)&pwi,  g_pw_i);
    cudaGetSymbolAddress((void**)&pgs,  g_gs);
    cudaGetSymbolAddress((void**)&pBu,  g_Bu);
    cudaGetSymbolAddress((void**)&pBi,  g_Bi);

    static const int SMEM_P = (3 * 128 * 36 + 3 * 32 * 72) * 4;    // 82944
    static const int SMEM_L = (2 * 128 * 68 + 16 * 72 + 128) * 4;
    cudaFuncSetAttribute(pgemm, cudaFuncAttributeMaxDynamicSharedMemorySize, SMEM_P);
    cudaFuncSetAttribute(layer_kernel<1>,
                         cudaFuncAttributeMaxDynamicSharedMemorySize, SMEM_L);
    cudaFuncSetAttribute(layer_kernel<0>,
                         cudaFuncAttributeMaxDynamicSharedMemorySize, SMEM_L);

    // fork/join resources (host objects; created per call, no device memory)
    cudaStream_t s2;
    cudaStreamCreateWithFlags(&s2, cudaStreamNonBlocking);
    cudaEvent_t evFork, evJoin;
    cudaEventCreateWithFlags(&evFork, cudaEventDisableTiming);
    cudaEventCreateWithFlags(&evJoin, cudaEventDisableTiming);

    // ---- pack dense padded B matrices (main stream) ----
    pack_kernel<<<(1152 * 64 + 255) / 256, 256>>>(Wpu, Wpi);

    // fork: item chain on s2 after pack
    cudaEventRecord(evFork, 0);
    cudaStreamWaitEvent(s2, evFork, 0);

    // ======== USER chain (main stream) ========
    PArgs t{};
    t.A0 = ufe; t.a0e = 64; t.a0rs = 64;
    t.a1b = 0; t.a1e = 0; t.a2b = 0; t.a2e = 0; t.A1 = ufe; t.A2 = ufe;
    t.B = Wpu + 64 * 64; t.bsy = 0; t.gs = nullptr;
    t.out = pfeu; t.ostride = 64; t.osy = 0;
    t.M = NFEAT; t.K = 64; t.scale = 0.1f;
    pgemm<<<dim3((NFEAT + 127) / 128, 1), 256, SMEM_P>>>(t);

    t.A0 = wemb; t.A1 = wemb; t.A2 = wemb; t.a0e = 32; t.a0rs = 32;
    t.B = Wpu + 128 * 64; t.bsy = 32 * 64;
    t.out = pwu; t.ostride = 192; t.osy = 64;
    t.M = VOCABC; t.K = 32; t.scale = 0.125f;
    pgemm<<<dim3((VOCABC + 127) / 128, 3), 256, SMEM_P>>>(t);

    gather_kernel<<<(N_USERC * 32 + 255) / 256, 256>>>(
        ufi, uti, unum, Wnu, bpu, bnu, pfeu, pwu, pgs, N_USERC);

    PArgs u{};
    u.A0 = uide; u.a0e = 64;  u.a0rs = 64;
    u.A1 = uw300; u.a1b = 64; u.a1e = 364; u.a1rs = 300;
    u.A2 = uide; u.a2b = 0; u.a2e = 0; u.a2rs = 0;
    u.B = pBu; u.bsy = 0; u.gs = pgs;
    u.out = px; u.ostride = 64; u.osy = 0;
    u.M = N_USERC; u.K = 384; u.scale = 1.f;
    pgemm<<<dim3((N_USERC + 127) / 128, 1), 256, SMEM_P>>>(u);

    // ======== ITEM chain (stream s2) ========
    PArgs ti2{};
    ti2.A0 = ife; ti2.a0e = 64; ti2.a0rs = 64;
    ti2.a1b = 0; ti2.a1e = 0; ti2.a2b = 0; ti2.a2e = 0; ti2.A1 = ife; ti2.A2 = ife;
    ti2.B = Wpi + 64 * 64; ti2.bsy = 0; ti2.gs = nullptr;
    ti2.out = pfei; ti2.ostride = 64; ti2.osy = 0;
    ti2.M = NFEAT; ti2.K = 64; ti2.scale = 0.1f;
    pgemm<<<dim3((NFEAT + 127) / 128, 1), 256, SMEM_P, s2>>>(ti2);

    ti2.A0 = wemb; ti2.A1 = wemb; ti2.A2 = wemb; ti2.a0e = 32; ti2.a0rs = 32;
    ti2.B = Wpi + 128 * 64; ti2.bsy = 32 * 64;
    ti2.out = pwi; ti2.ostride = 192; ti2.osy = 64;
    ti2.M = VOCABC; ti2.K = 32; ti2.scale = 0.125f;
    pgemm<<<dim3((VOCABC + 127) / 128, 3), 256, SMEM_P, s2>>>(ti2);

    gather_kernel<<<(M_ITEMC * 32 + 255) / 256, 256, 0, s2>>>(
        ifi, iti, inum, Wni, bpi, bni, pfei, pwi,
        pgs + (size_t)N_USERC * 64, M_ITEMC);

    PArgs v{};
    v.A0 = iide; v.a0e = 64;  v.a0rs = 64;
    v.A1 = iw300; v.a1b = 64; v.a1e = 364; v.a1rs = 300;
    v.A2 = is768; v.a2b = 368; v.a2e = 1136; v.a2rs = 768;
    v.B = pBi; v.bsy = 0; v.gs = pgs + (size_t)N_USERC * 64;
    v.out = px + (size_t)N_USERC * 64; v.ostride = 64; v.osy = 0;
    v.M = M_ITEMC; v.K = 1152; v.scale = 1.f;
    pgemm<<<dim3((M_ITEMC + 127) / 128, 1), 256, SMEM_P, s2>>>(v);

    // join: main stream waits for item chain
    cudaEventRecord(evJoin, s2);
    cudaStreamWaitEvent(0, evJoin, 0);

    // ---- layer 0 (fused mean+agg+concat GEMM), relu ----
    layer_kernel<1><<<(MROWS + 127) / 128, 256, SMEM_L>>>(
        neigh2, neigh1, seeds, Wv, bv, Ww, bw, ph, MROWS, 1);

    // ---- layer 1, no relu, writes output ----
    layer_kernel<0><<<(BSEED + 127) / 128, 256, SMEM_L>>>(
        nullptr, nullptr, nullptr, Wv + 64 * 64, bv + 64,
        Ww + 128 * 64, bw + 64, out, BSEED, 0);
}

// round 10
// speedup vs baseline: 1.5337x; 1.0174x over previous
#include <cuda_runtime.h>
#include <cuda_fp16.h>
#include <cstdint>
#include <cstddef>

#define N_USERC 100000
#define M_ITEMC 50000
#define N_NODEC 150000
#define DD      64
#define BSEED   2048
#define SNB     20
#define M1ROWS  (BSEED*SNB)          // 40960
#define MROWS   (BSEED*SNB + BSEED)  // 43008
#define NFEAT   30000
#define VOCABC  20000

// ---------------- device scratch ----------
__device__ float  g_x[(size_t)N_NODEC * DD];
__device__ float  g_h[(size_t)MROWS * DD];
__device__ __half g_pfe_u[(size_t)NFEAT * 64];
__device__ __half g_pfe_i[(size_t)NFEAT * 64];
__device__ __half g_pw_u[(size_t)VOCABC * 192];
__device__ __half g_pw_i[(size_t)VOCABC * 192];
__device__ float  g_gs[(size_t)N_NODEC * 64];
__device__ float  g_Bu[(size_t)384 * 64];
__device__ float  g_Bi[(size_t)1152 * 64];

__device__ __forceinline__ uint32_t f2tf(float v) {
    uint32_t r; asm("cvt.rna.tf32.f32 %0, %1;" : "=r"(r) : "f"(v)); return r;
}
__device__ __forceinline__ void mma_tf32(float c[4],
    uint32_t a0, uint32_t a1, uint32_t a2, uint32_t a3, uint32_t b0, uint32_t b1)
{
    asm volatile(
        "mma.sync.aligned.m16n8k8.row.col.f32.tf32.tf32.f32 "
        "{%0,%1,%2,%3},{%4,%5,%6,%7},{%8,%9},{%0,%1,%2,%3};"
        : "+f"(c[0]), "+f"(c[1]), "+f"(c[2]), "+f"(c[3])
        : "r"(a0), "r"(a1), "r"(a2), "r"(a3), "r"(b0), "r"(b1));
}
__device__ __forceinline__ uint32_t smem_u32(const void* p) {
    return (uint32_t)__cvta_generic_to_shared(p);
}
__device__ __forceinline__ void cp16(uint32_t dst, const void* src, int bytes) {
    asm volatile("cp.async.ca.shared.global [%0], [%1], 16, %2;\n"
                 :: "r"(dst), "l"(src), "r"(bytes));
}
__device__ __forceinline__ void cp_commit() {
    asm volatile("cp.async.commit_group;\n");
}
template<int N> __device__ __forceinline__ void cp_wait() {
    asm volatile("cp.async.wait_group %0;\n" :: "n"(N));
}

// =================== pipelined GEMM (3-stage): out = scale*A@B (+gs) ========
struct PArgs {
    const float *A0, *A1, *A2;
    int a0e, a1b, a1e, a2b, a2e;
    int a0rs, a1rs, a2rs;
    const float* B;  long bsy;
    const float* gs;
    void* out; int ostride; long osy;
    int M, K; float scale;
    int out_half;                  // 1 -> store __half, else float
};

__device__ __forceinline__ void compute32(float c[2][4][4],
    const float* Ad, const float* Bd, int wm, int wn, int lane)
{
    const int r0 = lane >> 2, q = lane & 3;
#pragma unroll
    for (int ks = 0; ks < 4; ks++) {
        const int kb = ks * 8;
        uint32_t a[2][4], b[4][2];
#pragma unroll
        for (int mi = 0; mi < 2; mi++) {
            int mr = wm * 32 + mi * 16 + r0;
            a[mi][0] = f2tf(Ad[mr * 36 + kb + q]);
            a[mi][1] = f2tf(Ad[(mr + 8) * 36 + kb + q]);
            a[mi][2] = f2tf(Ad[mr * 36 + kb + q + 4]);
            a[mi][3] = f2tf(Ad[(mr + 8) * 36 + kb + q + 4]);
        }
#pragma unroll
        for (int ni = 0; ni < 4; ni++) {
            int nc = wn * 32 + ni * 8 + r0;
            b[ni][0] = f2tf(Bd[(kb + q) * 72 + nc]);
            b[ni][1] = f2tf(Bd[(kb + q + 4) * 72 + nc]);
        }
#pragma unroll
        for (int mi = 0; mi < 2; mi++)
#pragma unroll
            for (int ni = 0; ni < 4; ni++)
                mma_tf32(c[mi][ni], a[mi][0], a[mi][1], a[mi][2], a[mi][3],
                         b[ni][0], b[ni][1]);
    }
}

__global__ void __launch_bounds__(256) pgemm(PArgs p)
{
    extern __shared__ float smp[];
    float* Asm = smp;                      // [3][128*36]
    float* Bsm = smp + 3 * 128 * 36;       // [3][32*72]

    const int tid = threadIdx.x, lane = tid & 31, wid = tid >> 5;
    const int wm = wid >> 1, wn = wid & 1;
    const int m0 = blockIdx.x * 128;
    const float* Bp = p.B + (size_t)blockIdx.y * p.bsy;

    auto issue = [&](int tile, int slot) {
        const int k0 = tile * 32;
        float* Ad = Asm + slot * (128 * 36);
        float* Bd = Bsm + slot * (32 * 72);
#pragma unroll
        for (int j = 0; j < 4; j++) {
            int ch = tid + j * 256;
            int r = ch >> 3, cq = ch & 7;
            int col = k0 + cq * 4;
            int row = m0 + r;
            const float* src = p.A0; int bytes = 0;
            if (row < p.M) {
                if (col < p.a0e) {
                    src = p.A0 + (size_t)row * p.a0rs + col; bytes = 16;
                } else if (col >= p.a1b && col < p.a1e) {
                    src = p.A1 + (size_t)row * p.a1rs + (col - p.a1b); bytes = 16;
                } else if (col >= p.a2b && col < p.a2e) {
                    src = p.A2 + (size_t)row * p.a2rs + (col - p.a2b); bytes = 16;
                }
            }
            cp16(smem_u32(Ad + r * 36 + cq * 4), src, bytes);
        }
#pragma unroll
        for (int j = 0; j < 2; j++) {
            int cb = tid + j * 256;
            int kr = cb >> 4, cq = cb & 15;
            cp16(smem_u32(Bd + kr * 72 + cq * 4),
                 Bp + (size_t)(k0 + kr) * 64 + cq * 4, 16);
        }
    };

    float c[2][4][4];
#pragma unroll
    for (int a = 0; a < 2; a++)
#pragma unroll
        for (int b = 0; b < 4; b++)
#pragma unroll
            for (int d = 0; d < 4; d++) c[a][b][d] = 0.f;

    const int nt = p.K / 32;
    issue(0, 0); cp_commit();
    if (nt > 1) { issue(1, 1); cp_commit(); }

    for (int t = 0; t < nt; t++) {
        if (t + 1 < nt) cp_wait<1>(); else cp_wait<0>();
        __syncthreads();
        if (t + 2 < nt) { issue(t + 2, (t + 2) % 3); cp_commit(); }
        const float* Ad = Asm + (t % 3) * (128 * 36);
        const float* Bd = Bsm + (t % 3) * (32 * 72);
        compute32(c, Ad, Bd, wm, wn, lane);
    }

    const long obase = (long)blockIdx.y * p.osy;
    const int r0 = lane >> 2, q = lane & 3;
#pragma unroll
    for (int mi = 0; mi < 2; mi++)
#pragma unroll
        for (int ni = 0; ni < 4; ni++) {
            int col = wn * 32 + ni * 8 + 2 * q;
            int row = m0 + wm * 32 + mi * 16 + r0;
#pragma unroll
            for (int h = 0; h < 2; h++) {
                int rr = row + h * 8;
                if (rr < p.M) {
                    float v0 = c[mi][ni][h * 2]     * p.scale;
                    float v1 = c[mi][ni][h * 2 + 1] * p.scale;
                    if (p.gs) {
                        float2 g = *reinterpret_cast<const float2*>(
                            p.gs + (size_t)rr * 64 + col);
                        v0 += g.x; v1 += g.y;
                    }
                    if (p.out_half) {
                        __half* ho = (__half*)p.out + obase +
                                     (size_t)rr * p.ostride + col;
                        *reinterpret_cast<__half2*>(ho) = __floats2half2_rn(v0, v1);
                    } else {
                        float* fo = (float*)p.out + obase +
                                    (size_t)rr * p.ostride + col;
                        *reinterpret_cast<float2*>(fo) = make_float2(v0, v1);
                    }
                }
            }
        }
}

// =================== pack padded dense B matrices ===========================
__global__ void pack_kernel(const float* __restrict__ Wpu,
                            const float* __restrict__ Wpi)
{
    int i = blockIdx.x * 256 + threadIdx.x;
    if (i < 384 * 64) {
        int r = i >> 6, n = i & 63; float v = 0.f;
        if (r < 64)       v = Wpu[(size_t)r * 64 + n];
        else if (r < 364) v = Wpu[(size_t)(r + 160) * 64 + n];
        g_Bu[i] = v;
    }
    if (i < 1152 * 64) {
        int r = i >> 6, n = i & 63; float v = 0.f;
        if (r < 64)                    v = Wpi[(size_t)r * 64 + n];
        else if (r < 364)              v = Wpi[(size_t)(r + 160) * 64 + n];
        else if (r >= 368 && r < 1136) v = Wpi[(size_t)(r + 156) * 64 + n];
        g_Bi[i] = v;
    }
}

// ========== gather kernel (warp per node; fp16 tables) =======================
__global__ void __launch_bounds__(256) gather_kernel(
    const int* __restrict__ fi, const int* __restrict__ ti,
    const float* __restrict__ numer, const float* __restrict__ Wnum,
    const float* __restrict__ bproj, const float* __restrict__ bnum,
    const __half* __restrict__ Pfe, const __half* __restrict__ Pw,
    float* __restrict__ gs, int M)
{
    int w = (blockIdx.x * blockDim.x + threadIdx.x) >> 5;
    int lane = threadIdx.x & 31;
    if (w >= M) return;
    int c2 = lane * 2;

    float2 acc;
    acc.x = __ldg(bproj + c2)     + __ldg(bnum + c2);
    acc.y = __ldg(bproj + c2 + 1) + __ldg(bnum + c2 + 1);

#pragma unroll
    for (int d = 0; d < 10; d++) {
        float nv = __ldg(numer + (size_t)w * 10 + d);
        float2 ww = *reinterpret_cast<const float2*>(Wnum + (size_t)d * 64 + c2);
        acc.x += nv * ww.x; acc.y += nv * ww.y;
    }
#pragma unroll
    for (int j = 0; j < 10; j++) {
        int ix = __ldg(fi + (size_t)w * 10 + j);
        __half2 hv = *reinterpret_cast<const __half2*>(Pfe + (size_t)ix * 64 + c2);
        float2 v = __half22float2(hv);
        acc.x += v.x; acc.y += v.y;
    }
#pragma unroll
    for (int s = 0; s < 3; s++) {
#pragma unroll
        for (int t = 0; t < 8; t++) {
            int ix = __ldg(ti + (size_t)w * 24 + s * 8 + t);
            __half2 hv = *reinterpret_cast<const __half2*>(
                Pw + (size_t)ix * 192 + s * 64 + c2);
            float2 v = __half22float2(hv);
            acc.x += v.x; acc.y += v.y;
        }
    }
    *reinterpret_cast<float2*>(gs + (size_t)w * 64 + c2) = acc;
}

// =================== fused SAGE layer ======================================
__device__ __forceinline__ void compute_tile68(float c[2][4][4],
    const uint32_t (*Asrc)[68], int kbase, const uint32_t (*Bs)[72],
    int wm, int wn, int lane)
{
    const int r0 = lane >> 2, q = lane & 3;
#pragma unroll
    for (int ks = 0; ks < 2; ks++) {
        const int kb = ks * 8;
        uint32_t a[2][4], b[4][2];
#pragma unroll
        for (int mi = 0; mi < 2; mi++) {
            int mr = wm * 32 + mi * 16 + r0;
            a[mi][0] = Asrc[mr][kbase + kb + q];
            a[mi][1] = Asrc[mr + 8][kbase + kb + q];
            a[mi][2] = Asrc[mr][kbase + kb + q + 4];
            a[mi][3] = Asrc[mr + 8][kbase + kb + q + 4];
        }
#pragma unroll
        for (int ni = 0; ni < 4; ni++) {
            int nc = wn * 32 + ni * 8 + r0;
            b[ni][0] = Bs[kb + q][nc];
            b[ni][1] = Bs[kb + q + 4][nc];
        }
#pragma unroll
        for (int mi = 0; mi < 2; mi++)
#pragma unroll
            for (int ni = 0; ni < 4; ni++)
                mma_tf32(c[mi][ni], a[mi][0], a[mi][1], a[mi][2], a[mi][3],
                         b[ni][0], b[ni][1]);
    }
}

template<int L0>
__global__ void __launch_bounds__(256) layer_kernel(
    const int* __restrict__ neigh2, const int* __restrict__ neigh1,
    const int* __restrict__ seeds,
    const float* __restrict__ Wv, const float* __restrict__ bv,
    const float* __restrict__ Ww, const float* __restrict__ bw,
    float* __restrict__ outp, int M, int relu)
{
    extern __shared__ uint32_t dsm[];
    uint32_t (*Ms)[68] = (uint32_t(*)[68])dsm;
    uint32_t (*Ss)[68] = (uint32_t(*)[68])(dsm + 128 * 68);
    uint32_t (*Bs)[72] = (uint32_t(*)[72])(dsm + 2 * 128 * 68);
    float* sbv = (float*)(dsm + 2 * 128 * 68 + 16 * 72);
    float* sbw = sbv + 64;

    const int tid = threadIdx.x, lane = tid & 31, wid = tid >> 5;
    const int wm = wid >> 1, wn = wid & 1;
    const int m0 = blockIdx.x * 128;

    if (tid < 64) { sbv[tid] = bv[tid]; sbw[tid] = bw[tid]; }

#pragma unroll 1
    for (int rr = 0; rr < 16; ++rr) {
        int ln = wid * 16 + rr;
        int r = m0 + ln;
        float ax = 0.f, ay = 0.f;
        float2 self = make_float2(0.f, 0.f);
        if (r < M) {
            if (L0) {
                const int* idx = (r < M1ROWS) ? (neigh2 + (size_t)r * SNB)
                                              : (neigh1 + (size_t)(r - M1ROWS) * SNB);
#pragma unroll
                for (int j = 0; j < SNB; j++) {
                    int n = __ldg(idx + j);
                    float2 v = *reinterpret_cast<const float2*>(g_x + (size_t)n * 64 + lane * 2);
                    ax += v.x; ay += v.y;
                }
                int sn = (r < M1ROWS) ? __ldg(neigh1 + r) : __ldg(seeds + r - M1ROWS);
                self = *reinterpret_cast<const float2*>(g_x + (size_t)sn * 64 + lane * 2);
            } else {
#pragma unroll
                for (int j = 0; j < SNB; j++) {
                    float2 v = *reinterpret_cast<const float2*>(
                        g_h + (size_t)(r * SNB + j) * 64 + lane * 2);
                    ax += v.x; ay += v.y;
                }
                self = *reinterpret_cast<const float2*>(
                    g_h + (size_t)(M1ROWS + r) * 64 + lane * 2);
            }
            ax *= 0.05f; ay *= 0.05f;
        }
        Ms[ln][lane * 2]     = f2tf(ax);
        Ms[ln][lane * 2 + 1] = f2tf(ay);
        Ss[ln][lane * 2]     = f2tf(self.x);
        Ss[ln][lane * 2 + 1] = f2tf(self.y);
    }

    float ca[2][4][4];
#pragma unroll
    for (int a = 0; a < 2; a++)
#pragma unroll
        for (int b = 0; b < 4; b++)
#pragma unroll
            for (int d = 0; d < 4; d++) ca[a][b][d] = 0.f;

    for (int k0 = 0; k0 < 64; k0 += 16) {
        __syncthreads();
        for (int i = tid; i < 16 * 64; i += 256) {
            int kk = i >> 6, n = i & 63;
            Bs[kk][n] = f2tf(Wv[(size_t)(k0 + kk) * 64 + n]);
        }
        __syncthreads();
        compute_tile68(ca, Ms, k0, Bs, wm, wn, lane);
    }
    __syncthreads();

    {
        const int r0 = lane >> 2, q = lane & 3;
#pragma unroll
        for (int mi = 0; mi < 2; mi++)
#pragma unroll
            for (int ni = 0; ni < 4; ni++) {
                int col = wn * 32 + ni * 8 + 2 * q;
                int lr = wm * 32 + mi * 16 + r0;
#pragma unroll
                for (int h = 0; h < 2; h++) {
                    int lrow = lr + h * 8;
                    Ms[lrow][col]     = f2tf(ca[mi][ni][h * 2]     + sbv[col]);
                    Ms[lrow][col + 1] = f2tf(ca[mi][ni][h * 2 + 1] + sbv[col + 1]);
                }
            }
    }
    __syncthreads();

    float ch[2][4][4];
#pragma unroll
    for (int a = 0; a < 2; a++)
#pragma unroll
        for (int b = 0; b < 4; b++)
#pragma unroll
            for (int d = 0; d < 4; d++) ch[a][b][d] = 0.f;

    for (int k0 = 0; k0 < 128; k0 += 16) {
        __syncthreads();
        for (int i = tid; i < 16 * 64; i += 256) {
            int kk = i >> 6, n = i & 63;
            Bs[kk][n] = f2tf(Ww[(size_t)(k0 + kk) * 64 + n]);
        }
        __syncthreads();
        if (k0 < 64) compute_tile68(ch, Ss, k0,      Bs, wm, wn, lane);
        else         compute_tile68(ch, Ms, k0 - 64, Bs, wm, wn, lane);
    }

    const int r0 = lane >> 2, q = lane & 3;
#pragma unroll
    for (int mi = 0; mi < 2; mi++)
#pragma unroll
        for (int ni = 0; ni < 4; ni++) {
            int col = wn * 32 + ni * 8 + 2 * q;
            int row = m0 + wm * 32 + mi * 16 + r0;
#pragma unroll
            for (int h = 0; h < 2; h++) {
                int rr = row + h * 8;
                if (rr < M) {
                    float v0 = ch[mi][ni][h * 2]     + sbw[col];
                    float v1 = ch[mi][ni][h * 2 + 1] + sbw[col + 1];
                    if (relu) { v0 = fmaxf(v0, 0.f); v1 = fmaxf(v1, 0.f); }
                    *reinterpret_cast<float2*>(outp + (size_t)rr * 64 + col) =
                        make_float2(v0, v1);
                }
            }
        }
}

// ============================ launch =========================================
extern "C" void kernel_launch(void* const* d_in, const int* in_sizes, int n_in,
                              void* d_out, int out_size)
{
    const int*   seeds  = (const int*)d_in[0];
    const int*   neigh1 = (const int*)d_in[1];
    const int*   neigh2 = (const int*)d_in[2];
    const int*   ufi    = (const int*)d_in[3];
    const int*   ifi    = (const int*)d_in[4];
    const int*   uti    = (const int*)d_in[5];
    const int*   iti    = (const int*)d_in[6];
    const float* uide   = (const float*)d_in[7];
    const float* iide   = (const float*)d_in[8];
    const float* ufe    = (const float*)d_in[9];
    const float* ife    = (const float*)d_in[10];
    const float* wemb   = (const float*)d_in[11];
    const float* uw300  = (const float*)d_in[12];
    const float* iw300  = (const float*)d_in[13];
    const float* is768  = (const float*)d_in[14];
    const float* unum   = (const float*)d_in[15];
    const float* inum   = (const float*)d_in[16];
    const float* Wnu    = (const float*)d_in[17];
    const float* bnu    = (const float*)d_in[18];
    const float* Wni    = (const float*)d_in[19];
    const float* bni    = (const float*)d_in[20];
    const float* Wpu    = (const float*)d_in[21];
    const float* bpu    = (const float*)d_in[22];
    const float* Wpi    = (const float*)d_in[23];
    const float* bpi    = (const float*)d_in[24];
    const float* Ww     = (const float*)d_in[25];
    const float* bw     = (const float*)d_in[26];
    const float* Wv     = (const float*)d_in[27];
    const float* bv     = (const float*)d_in[28];
    float* out = (float*)d_out;

    float *px, *ph, *pgs, *pBu, *pBi;
    __half *pfeu, *pfei, *pwu, *pwi;
    cudaGetSymbolAddress((void**)&px,   g_x);
    cudaGetSymbolAddress((void**)&ph,   g_h);
    cudaGetSymbolAddress((void**)&pfeu, g_pfe_u);
    cudaGetSymbolAddress((void**)&pfei, g_pfe_i);
    cudaGetSymbolAddress((void**)&pwu,  g_pw_u);
    cudaGetSymbolAddress((void**)&pwi,  g_pw_i);
    cudaGetSymbolAddress((void**)&pgs,  g_gs);
    cudaGetSymbolAddress((void**)&pBu,  g_Bu);
    cudaGetSymbolAddress((void**)&pBi,  g_Bi);

    static const int SMEM_P = (3 * 128 * 36 + 3 * 32 * 72) * 4;    // 82944
    static const int SMEM_L = (2 * 128 * 68 + 16 * 72 + 128) * 4;
    cudaFuncSetAttribute(pgemm, cudaFuncAttributeMaxDynamicSharedMemorySize, SMEM_P);
    cudaFuncSetAttribute(layer_kernel<1>,
                         cudaFuncAttributeMaxDynamicSharedMemorySize, SMEM_L);
    cudaFuncSetAttribute(layer_kernel<0>,
                         cudaFuncAttributeMaxDynamicSharedMemorySize, SMEM_L);

    cudaStream_t s2;
    cudaStreamCreateWithFlags(&s2, cudaStreamNonBlocking);
    cudaEvent_t evFork, evJoin;
    cudaEventCreateWithFlags(&evFork, cudaEventDisableTiming);
    cudaEventCreateWithFlags(&evJoin, cudaEventDisableTiming);

    // ---- pack dense padded B matrices (main stream) ----
    pack_kernel<<<(1152 * 64 + 255) / 256, 256>>>(Wpu, Wpi);

    cudaEventRecord(evFork, 0);
    cudaStreamWaitEvent(s2, evFork, 0);

    // ======== USER chain (main stream) ========
    PArgs t{};
    t.A0 = ufe; t.a0e = 64; t.a0rs = 64;
    t.a1b = 0; t.a1e = 0; t.a2b = 0; t.a2e = 0; t.A1 = ufe; t.A2 = ufe;
    t.B = Wpu + 64 * 64; t.bsy = 0; t.gs = nullptr;
    t.out = pfeu; t.ostride = 64; t.osy = 0;
    t.M = NFEAT; t.K = 64; t.scale = 0.1f; t.out_half = 1;
    pgemm<<<dim3((NFEAT + 127) / 128, 1), 256, SMEM_P>>>(t);

    t.A0 = wemb; t.A1 = wemb; t.A2 = wemb; t.a0e = 32; t.a0rs = 32;
    t.B = Wpu + 128 * 64; t.bsy = 32 * 64;
    t.out = pwu; t.ostride = 192; t.osy = 64;
    t.M = VOCABC; t.K = 32; t.scale = 0.125f; t.out_half = 1;
    pgemm<<<dim3((VOCABC + 127) / 128, 3), 256, SMEM_P>>>(t);

    gather_kernel<<<(N_USERC * 32 + 255) / 256, 256>>>(
        ufi, uti, unum, Wnu, bpu, bnu, pfeu, pwu, pgs, N_USERC);

    PArgs u{};
    u.A0 = uide; u.a0e = 64;  u.a0rs = 64;
    u.A1 = uw300; u.a1b = 64; u.a1e = 364; u.a1rs = 300;
    u.A2 = uide; u.a2b = 0; u.a2e = 0; u.a2rs = 0;
    u.B = pBu; u.bsy = 0; u.gs = pgs;
    u.out = px; u.ostride = 64; u.osy = 0;
    u.M = N_USERC; u.K = 384; u.scale = 1.f; u.out_half = 0;
    pgemm<<<dim3((N_USERC + 127) / 128, 1), 256, SMEM_P>>>(u);

    // ======== ITEM chain (stream s2) ========
    PArgs ti2{};
    ti2.A0 = ife; ti2.a0e = 64; ti2.a0rs = 64;
    ti2.a1b = 0; ti2.a1e = 0; ti2.a2b = 0; ti2.a2e = 0; ti2.A1 = ife; ti2.A2 = ife;
    ti2.B = Wpi + 64 * 64; ti2.bsy = 0; ti2.gs = nullptr;
    ti2.out = pfei; ti2.ostride = 64; ti2.osy = 0;
    ti2.M = NFEAT; ti2.K = 64; ti2.scale = 0.1f; ti2.out_half = 1;
    pgemm<<<dim3((NFEAT + 127) / 128, 1), 256, SMEM_P, s2>>>(ti2);

    ti2.A0 = wemb; ti2.A1 = wemb; ti2.A2 = wemb; ti2.a0e = 32; ti2.a0rs = 32;
    ti2.B = Wpi + 128 * 64; ti2.bsy = 32 * 64;
    ti2.out = pwi; ti2.ostride = 192; ti2.osy = 64;
    ti2.M = VOCABC; ti2.K = 32; ti2.scale = 0.125f; ti2.out_half = 1;
    pgemm<<<dim3((VOCABC + 127) / 128, 3), 256, SMEM_P, s2>>>(ti2);

    gather_kernel<<<(M_ITEMC * 32 + 255) / 256, 256, 0, s2>>>(
        ifi, iti, inum, Wni, bpi, bni, pfei, pwi,
        pgs + (size_t)N_USERC * 64, M_ITEMC);

    PArgs v{};
    v.A0 = iide; v.a0e = 64;  v.a0rs = 64;
    v.A1 = iw300; v.a1b = 64; v.a1e = 364; v.a1rs = 300;
    v.A2 = is768; v.a2b = 368; v.a2e = 1136; v.a2rs = 768;
    v.B = pBi; v.bsy = 0; v.gs = pgs + (size_t)N_USERC * 64;
    v.out = px + (size_t)N_USERC * 64; v.ostride = 64; v.osy = 0;
    v.M = M_ITEMC; v.K = 1152; v.scale = 1.f; v.out_half = 0;
    pgemm<<<dim3((M_ITEMC + 127) / 128, 1), 256, SMEM_P, s2>>>(v);

    cudaEventRecord(evJoin, s2);
    cudaStreamWaitEvent(0, evJoin, 0);

    // ---- layer 0 (fused mean+agg+concat GEMM), relu ----
    layer_kernel<1><<<(MROWS + 127) / 128, 256, SMEM_L>>>(
        neigh2, neigh1, seeds, Wv, bv, Ww, bw, ph, MROWS, 1);

    // ---- layer 1, no relu, writes output ----
    layer_kernel<0><<<(BSEED + 127) / 128, 256, SMEM_L>>>(
        nullptr, nullptr, nullptr, Wv + 64 * 64, bv + 64,
        Ww + 128 * 64, bw + 64, out, BSEED, 0);
}